// round 13
// baseline (speedup 1.0000x reference)
#include <cuda_runtime.h>
#include <cuda_fp16.h>
#include <cstdint>
#include <math.h>

#define B_  8192
#define H_  512
#define G3_ 1536
#define V_  2048
#define T_  24

// residual scale 2^11
#define RSC   2048.0f
#define RSCI  4.8828125e-4f

// ---------------------------------------------------------------------------
// Scratch (device globals: allocation-free)
// ---------------------------------------------------------------------------
__device__ float g_h[B_ * H_];
__device__ float g_gi[B_ * G3_];
__device__ float g_gh[B_ * G3_];
__device__ float g_logits[B_ * V_];
__device__ float g_gum[(size_t)B_ * V_];   // per-step Gumbel noise
__device__ unsigned int g_cnt[B_ / 128];   // per-m-block arrival counters (zero-init)

// scaled fp16x2 splits: X = X0 + X1 * 2^-11
__device__ __half g_IA0[B_ * H_],  g_IA1[B_ * H_];
__device__ __half g_HA0[B_ * H_],  g_HA1[B_ * H_];
__device__ __half g_Wih0[G3_ * H_], g_Wih1[G3_ * H_];
__device__ __half g_Whh0[G3_ * H_], g_Whh1[G3_ * H_];
__device__ __half g_Wo0[V_ * H_],   g_Wo1[V_ * H_];

// ---------------------------------------------------------------------------
// Threefry-2x32 (exact JAX replica)
// ---------------------------------------------------------------------------
__host__ __device__ __forceinline__ uint32_t rotl32(uint32_t v, int r) {
    return (v << r) | (v >> (32 - r));
}

__host__ __device__ __forceinline__ void tf2x32(uint32_t k0, uint32_t k1,
                                                uint32_t c0, uint32_t c1,
                                                uint32_t &o0, uint32_t &o1) {
    const uint32_t k2 = k0 ^ k1 ^ 0x1BD11BDAu;
    uint32_t a = c0, b = c1;
    a += k0; b += k1;
#define TFR(r) { a += b; b = rotl32(b, r); b ^= a; }
    TFR(13) TFR(15) TFR(26) TFR(6)
    a += k1; b += k2 + 1u;
    TFR(17) TFR(29) TFR(16) TFR(24)
    a += k2; b += k0 + 2u;
    TFR(13) TFR(15) TFR(26) TFR(6)
    a += k0; b += k1 + 3u;
    TFR(17) TFR(29) TFR(16) TFR(24)
    a += k1; b += k2 + 4u;
    TFR(13) TFR(15) TFR(26) TFR(6)
    a += k2; b += k0 + 5u;
#undef TFR
    o0 = a; o1 = b;
}

__device__ __forceinline__ float gumbelf(uint32_t bits) {
    float f = __uint_as_float((bits >> 9) | 0x3F800000u) - 1.0f;
    float u = fmaxf(1.17549435082228751e-38f, f);
    return -logf(-logf(u));
}

__device__ __forceinline__ float sigx(float v) {
    return 0.5f * tanhf(0.5f * v) + 0.5f;
}

// scaled fp16x2 split: x ≈ h0 + h1 * 2^-11
__device__ __forceinline__ void split2(float x, __half &h0, __half &h1) {
    h0 = __float2half_rn(x);
    float r = x - __half2float(h0);
    h1 = __float2half_rn(r * RSC);
}

// ---------------------------------------------------------------------------
// mma.sync / ldmatrix / cp.async primitives
// ---------------------------------------------------------------------------
__device__ __forceinline__ uint32_t smem_u32(const void* p) {
    uint32_t a;
    asm("{ .reg .u64 t; cvta.to.shared.u64 t, %1; cvt.u32.u64 %0, t; }"
        : "=r"(a) : "l"(p));
    return a;
}

__device__ __forceinline__ void ldsm4(uint32_t &r0, uint32_t &r1,
                                      uint32_t &r2, uint32_t &r3, uint32_t addr) {
    asm volatile("ldmatrix.sync.aligned.m8n8.x4.shared.b16 {%0,%1,%2,%3}, [%4];"
                 : "=r"(r0), "=r"(r1), "=r"(r2), "=r"(r3) : "r"(addr));
}

__device__ __forceinline__ void mma16816(float *d, const uint32_t *a,
                                         uint32_t b0, uint32_t b1) {
    asm volatile(
        "mma.sync.aligned.m16n8k16.row.col.f32.f16.f16.f32 "
        "{%0,%1,%2,%3},{%4,%5,%6,%7},{%8,%9},{%0,%1,%2,%3};"
        : "+f"(d[0]), "+f"(d[1]), "+f"(d[2]), "+f"(d[3])
        : "r"(a[0]), "r"(a[1]), "r"(a[2]), "r"(a[3]), "r"(b0), "r"(b1));
}

__device__ __forceinline__ void cp16(uint32_t saddr, const void *g) {
    asm volatile("cp.async.cg.shared.global [%0], [%1], 16;"
                 :: "r"(saddr), "l"(g));
}
#define CP_COMMIT() asm volatile("cp.async.commit_group;" ::: "memory")
#define CP_WAIT(n)  asm volatile("cp.async.wait_group %0;" :: "n"(n) : "memory")

struct GemmOps { const __half *a0, *a1, *b0, *b1;
                 const float *bias; float *c; };

#define TILE_B   8192
#define STAGE_B  (4 * TILE_B)
#define SMEM_TOT (2 * STAGE_B)

// ---------------------------------------------------------------------------
// Shared GEMM tile body (128x128 CTA tile, 512 thr, 16 warps 4x4).
// Proven at rel_err 1.8e-7 (R9/R11). Unchanged.
// ---------------------------------------------------------------------------
__device__ __forceinline__ void gemm_tile_body(const GemmOps &op, int m0, int n0,
                                               int N, char *smem) {
    const uint32_t sb = smem_u32(smem);
    const int tid = threadIdx.x;
    const int wid = tid >> 5;
    const int lane = tid & 31;
    const int wm = wid >> 2;
    const int wn = wid & 3;

    const __half *mats[4] = {
        op.a0 + (size_t)m0 * 512, op.a1 + (size_t)m0 * 512,
        op.b0 + (size_t)n0 * 512, op.b1 + (size_t)n0 * 512};

    auto issue = [&](int ch, int buf) {
        const uint32_t bbase = sb + (uint32_t)buf * STAGE_B;
#pragma unroll
        for (int s = 0; s < 4; ++s) {
            int seg = tid + s * 512;
            int m = seg >> 9;
            int w = seg & 511;
            int row = w >> 2;
            int u = w & 3;
            uint32_t bo = (uint32_t)(row << 6) + (uint32_t)(u << 4);
            uint32_t sw = bo ^ ((bo >> 3) & 0x30u);
            cp16(bbase + m * TILE_B + sw,
                 mats[m] + (size_t)row * 512 + (ch << 5) + (u << 3));
        }
        CP_COMMIT();
    };

    float hi[2][4][4], lo[2][4][4];
#pragma unroll
    for (int i = 0; i < 2; i++)
#pragma unroll
        for (int j = 0; j < 4; j++)
#pragma unroll
            for (int k = 0; k < 4; k++) { hi[i][j][k] = 0.0f; lo[i][j][k] = 0.0f; }

    issue(0, 0);

#pragma unroll 1
    for (int ch = 0; ch < 16; ++ch) {
        const int buf = ch & 1;
        if (ch < 15) { issue(ch + 1, buf ^ 1); CP_WAIT(1); }
        else         { CP_WAIT(0); }
        __syncthreads();

        const uint32_t stage = sb + (uint32_t)buf * STAGE_B;

#pragma unroll
        for (int ks = 0; ks < 2; ++ks) {
            const uint32_t kb = (uint32_t)(ks * 32) + (uint32_t)((lane >> 4) << 4);

            uint32_t bq[2][2][4];
#pragma unroll
            for (int sp = 0; sp < 2; ++sp) {
                const uint32_t Bt = stage + (2 + sp) * TILE_B;
#pragma unroll
                for (int nh = 0; nh < 2; ++nh) {
                    uint32_t row = (uint32_t)(wn * 32 + nh * 16 + (lane & 15));
                    uint32_t bo = (row << 6) + kb;
                    uint32_t sw = bo ^ ((bo >> 3) & 0x30u);
                    ldsm4(bq[sp][nh][0], bq[sp][nh][1], bq[sp][nh][2], bq[sp][nh][3],
                          Bt + sw);
                }
            }
            uint32_t af[2][2][4];
#pragma unroll
            for (int sp = 0; sp < 2; ++sp) {
                const uint32_t At = stage + sp * TILE_B;
#pragma unroll
                for (int mi = 0; mi < 2; ++mi) {
                    uint32_t row = (uint32_t)(wm * 32 + mi * 16 + (lane & 15));
                    uint32_t bo = (row << 6) + kb;
                    uint32_t sw = bo ^ ((bo >> 3) & 0x30u);
                    ldsm4(af[sp][mi][0], af[sp][mi][1], af[sp][mi][2], af[sp][mi][3],
                          At + sw);
                }
            }
#pragma unroll
            for (int mi = 0; mi < 2; ++mi)
#pragma unroll
                for (int ni = 0; ni < 4; ++ni) {
                    uint32_t b00 = bq[0][ni >> 1][ni & 1];
                    uint32_t b01 = bq[0][ni >> 1][(ni & 1) + 2];
                    uint32_t b10 = bq[1][ni >> 1][ni & 1];
                    uint32_t b11 = bq[1][ni >> 1][(ni & 1) + 2];
                    mma16816(hi[mi][ni], af[0][mi], b00, b01);
                    mma16816(lo[mi][ni], af[0][mi], b10, b11);
                    mma16816(lo[mi][ni], af[1][mi], b00, b01);
                }
        }
        __syncthreads();
    }

    const int tr = lane >> 2;
    const int tc = (lane & 3) << 1;
#pragma unroll
    for (int ni = 0; ni < 4; ++ni) {
        const int col = n0 + wn * 32 + ni * 8 + tc;
        const float bx = op.bias[col];
        const float by = op.bias[col + 1];
#pragma unroll
        for (int mi = 0; mi < 2; ++mi) {
            const int r0 = m0 + wm * 32 + mi * 16 + tr;
            float2 v0, v1;
            v0.x = fmaf(lo[mi][ni][0], RSCI, hi[mi][ni][0]) + bx;
            v0.y = fmaf(lo[mi][ni][1], RSCI, hi[mi][ni][1]) + by;
            v1.x = fmaf(lo[mi][ni][2], RSCI, hi[mi][ni][2]) + bx;
            v1.y = fmaf(lo[mi][ni][3], RSCI, hi[mi][ni][3]) + by;
            *(float2 *)(op.c + (size_t)r0 * N + col) = v0;
            *(float2 *)(op.c + (size_t)(r0 + 8) * N + col) = v1;
        }
    }
}

// ---------------------------------------------------------------------------
// Gates GEMM + Gumbel generation, one launch (R11-proven):
//   blocks [0,768)      : gi tiles  (IA @ Wih^T)
//   blocks [768,1536)   : gh tiles  (HA @ Whh^T)
//   blocks [1536,3584)  : Gumbel(t) noise -> g_gum
// ---------------------------------------------------------------------------
__global__ void __launch_bounds__(512)
gates_gum(GemmOps opIH, GemmOps opHH, uint32_t k0, uint32_t k1) {
    extern __shared__ char smem[];
    const int bid = blockIdx.x;
    if (bid < 1536) {
        const GemmOps &op = (bid < 768) ? opIH : opHH;
        const int local = (bid < 768) ? bid : bid - 768;
        gemm_tile_body(op, (local / 12) << 7, (local % 12) << 7, G3_, smem);
        return;
    }
    const uint32_t gb = (uint32_t)(bid - 1536);
    const uint32_t base = gb * 8192u + (uint32_t)threadIdx.x;
#pragma unroll
    for (int k = 0; k < 16; ++k) {
        uint32_t j = base + (uint32_t)(k << 9);
        uint32_t o0, o1;
        tf2x32(k0, k1, 0u, j, o0, o1);
        g_gum[j] = gumbelf(o0 ^ o1);
    }
}

// ---------------------------------------------------------------------------
// Fused logits GEMM + sampling. Grid (16 n-tiles, 64 m-tiles).
// Each CTA computes its 128x128 logits tile, then the LAST CTA to finish an
// m-block (atomic counter over the 16 column tiles) samples those 128 rows:
// 16 warps x 8 rows, warp-private reductions (no cross-warp sync).
// ---------------------------------------------------------------------------
__global__ void __launch_bounds__(512)
logits_sample(GemmOps op, const float *__restrict__ etab, int t,
              float *__restrict__ oSeq, float *__restrict__ oLp,
              float *__restrict__ oEnt) {
    extern __shared__ char smem[];
    const int m0 = blockIdx.y << 7;
    gemm_tile_body(op, m0, blockIdx.x << 7, V_, smem);

    // release epilogue stores, then count arrivals on this m-block
    __threadfence();
    __syncthreads();
    __shared__ int lastFlag;
    if (threadIdx.x == 0) {
        unsigned int old = atomicAdd(&g_cnt[blockIdx.y], 1u);
        lastFlag = (old == 15u);
        if (old == 15u) g_cnt[blockIdx.y] = 0u;   // reset for next launch
    }
    __syncthreads();
    if (!lastFlag) return;
    __threadfence();   // acquire: other CTAs' logits stores now visible

    const int wid = threadIdx.x >> 5;
    const int lane = threadIdx.x & 31;

#pragma unroll 1
    for (int k = 0; k < 8; ++k) {
        const int row = m0 + wid * 8 + k;
        const float *L = g_logits + (size_t)row * V_;
        const float *G = g_gum + (size_t)row * V_;

        // pass 1: row max (order-independent)
        float m = -INFINITY;
#pragma unroll 8
        for (int j = 0; j < 64; ++j) m = fmaxf(m, L[lane + (j << 5)]);
#pragma unroll
        for (int o = 16; o > 0; o >>= 1) m = fmaxf(m, __shfl_xor_sync(~0u, m, o));

        // pass 2: S = sum e^(x-m), W = sum e^(x-m)*(x-m)
        float S = 0.0f, W = 0.0f;
#pragma unroll 4
        for (int j = 0; j < 64; ++j) {
            float x = L[lane + (j << 5)];
            float d = x - m;
            float e = expf(d);
            S += e;
            W += e * d;
        }
#pragma unroll
        for (int o = 16; o > 0; o >>= 1) {
            S += __shfl_xor_sync(~0u, S, o);
            W += __shfl_xor_sync(~0u, W, o);
        }
        float Lg = logf(S);
        float ent = Lg - W / S;    // = -sum p*lsm

        // pass 3: gumbel argmax over lsm + g (first-index tie-break) + lp
        float bv = -INFINITY, blsm = 0.0f;
        int bi = 0x7FFFFFFF;
#pragma unroll 4
        for (int j = 0; j < 64; ++j) {
            int v = lane + (j << 5);
            float lsm = (L[v] - m) - Lg;
            float val = lsm + G[v];
            if (val > bv) { bv = val; bi = v; blsm = lsm; }
        }
#pragma unroll
        for (int o = 16; o > 0; o >>= 1) {
            float v2 = __shfl_xor_sync(~0u, bv, o);
            int   i2 = __shfl_xor_sync(~0u, bi, o);
            float l2 = __shfl_xor_sync(~0u, blsm, o);
            if (v2 > bv || (v2 == bv && i2 < bi)) { bv = v2; bi = i2; blsm = l2; }
        }
        if (lane == 0) {
            oSeq[(size_t)row * T_ + t] = (float)bi;
            oLp [(size_t)row * T_ + t] = blsm;
            oEnt[(size_t)row * T_ + t] = ent;
        }

        // embedding gather -> next step input splits
        const int tok = bi;   // converged across lanes after xor tree
        for (int c = lane; c < 512; c += 32) {
            float v = etab[(size_t)tok * 512 + c];
            __half h0, h1;
            split2(v, h0, h1);
            size_t idx = (size_t)row * H_ + c;
            g_IA0[idx] = h0; g_IA1[idx] = h1;
        }
    }
}

// ---------------------------------------------------------------------------
// GRU cell + LayerNorm; writes fp32 h AND its fp16x2 splits.
// ---------------------------------------------------------------------------
__global__ void __launch_bounds__(512) gru_ln(const float *__restrict__ ln_g,
                                              const float *__restrict__ ln_b) {
    const int b = blockIdx.x;
    const int j = threadIdx.x;
    const int wid = j >> 5;
    const int lane = j & 31;
    __shared__ float ws[16];
    __shared__ float bc[2];

    const float *gib = g_gi + (size_t)b * G3_;
    const float *ghb = g_gh + (size_t)b * G3_;
    float hv = g_h[(size_t)b * H_ + j];

    float r = sigx(gib[j] + ghb[j]);
    float z = sigx(gib[512 + j] + ghb[512 + j]);
    float n = tanhf(gib[1024 + j] + r * ghb[1024 + j]);
    float hn = (1.0f - z) * n + z * hv;

    float s = hn;
#pragma unroll
    for (int o = 16; o > 0; o >>= 1) s += __shfl_xor_sync(0xFFFFFFFFu, s, o);
    if (lane == 0) ws[wid] = s;
    __syncthreads();
    if (j < 32) {
        float v = (j < 16) ? ws[j] : 0.0f;
#pragma unroll
        for (int o = 8; o > 0; o >>= 1) v += __shfl_xor_sync(0xFFFFFFFFu, v, o);
        if (j == 0) bc[0] = v * (1.0f / 512.0f);
    }
    __syncthreads();
    float mu = bc[0];

    float d = hn - mu;
    s = d * d;
#pragma unroll
    for (int o = 16; o > 0; o >>= 1) s += __shfl_xor_sync(0xFFFFFFFFu, s, o);
    if (lane == 0) ws[wid] = s;
    __syncthreads();
    if (j < 32) {
        float v = (j < 16) ? ws[j] : 0.0f;
#pragma unroll
        for (int o = 8; o > 0; o >>= 1) v += __shfl_xor_sync(0xFFFFFFFFu, v, o);
        if (j == 0) bc[1] = v * (1.0f / 512.0f);
    }
    __syncthreads();
    float var = bc[1];

    float out = d * rsqrtf(var + 1e-5f) * ln_g[j] + ln_b[j];
    size_t idx = (size_t)b * H_ + j;
    g_h[idx] = out;
    __half h0, h1;
    split2(out, h0, h1);
    g_HA0[idx] = h0; g_HA1[idx] = h1;
}

// ---------------------------------------------------------------------------
// Init + weight splits
// ---------------------------------------------------------------------------
__global__ void __launch_bounds__(256) init_k(const float *__restrict__ emb,
                                              const float *__restrict__ sos) {
    int i = blockIdx.x * 256 + threadIdx.x;
    float x = emb[i];
    g_h[i] = x;
    __half h0, h1;
    split2(x, h0, h1);
    g_HA0[i] = h0; g_HA1[i] = h1;

    float y = sos[i & 511];
    split2(y, h0, h1);
    g_IA0[i] = h0; g_IA1[i] = h1;
}

__global__ void __launch_bounds__(256) splitw_k(const float *__restrict__ src,
                                                __half *d0, __half *d1, int n) {
    int i = blockIdx.x * 256 + threadIdx.x;
    if (i < n) {
        __half a, b;
        split2(src[i], a, b);
        d0[i] = a; d1[i] = b;
    }
}

// ---------------------------------------------------------------------------
// Host launcher (graph-capturable; single stream, no allocations)
// ---------------------------------------------------------------------------
extern "C" void kernel_launch(void* const* d_in, const int* in_sizes, int n_in,
                              void* d_out, int out_size) {
    (void)in_sizes; (void)n_in; (void)out_size;
    const float* embedding = (const float*)d_in[0];
    const float* sos   = (const float*)d_in[2];
    const float* W_ih  = (const float*)d_in[3];
    const float* W_hh  = (const float*)d_in[4];
    const float* b_ih  = (const float*)d_in[5];
    const float* b_hh  = (const float*)d_in[6];
    const float* ln_g  = (const float*)d_in[7];
    const float* ln_b  = (const float*)d_in[8];
    const float* W_out = (const float*)d_in[9];
    const float* b_out = (const float*)d_in[10];
    const float* etab  = (const float*)d_in[11];

    float* out  = (float*)d_out;
    float* oSeq = out;
    float* oLp  = out + (size_t)B_ * T_;
    float* oEnt = out + (size_t)2 * B_ * T_;

    cudaFuncSetAttribute(gates_gum, cudaFuncAttributeMaxDynamicSharedMemorySize,
                         SMEM_TOT);
    cudaFuncSetAttribute(logits_sample,
                         cudaFuncAttributeMaxDynamicSharedMemorySize, SMEM_TOT);

    float *pgi, *pgh, *plog;
    cudaGetSymbolAddress((void**)&pgi,  g_gi);
    cudaGetSymbolAddress((void**)&pgh,  g_gh);
    cudaGetSymbolAddress((void**)&plog, g_logits);

    __half *ia0, *ia1, *ha0, *ha1;
    __half *wih0, *wih1, *whh0, *whh1, *wo0, *wo1;
    cudaGetSymbolAddress((void**)&ia0, g_IA0); cudaGetSymbolAddress((void**)&ia1, g_IA1);
    cudaGetSymbolAddress((void**)&ha0, g_HA0); cudaGetSymbolAddress((void**)&ha1, g_HA1);
    cudaGetSymbolAddress((void**)&wih0, g_Wih0); cudaGetSymbolAddress((void**)&wih1, g_Wih1);
    cudaGetSymbolAddress((void**)&whh0, g_Whh0); cudaGetSymbolAddress((void**)&whh1, g_Whh1);
    cudaGetSymbolAddress((void**)&wo0, g_Wo0); cudaGetSymbolAddress((void**)&wo1, g_Wo1);

    splitw_k<<<(G3_ * H_ + 255) / 256, 256>>>(W_ih,  wih0, wih1, G3_ * H_);
    splitw_k<<<(G3_ * H_ + 255) / 256, 256>>>(W_hh,  whh0, whh1, G3_ * H_);
    splitw_k<<<(V_  * H_ + 255) / 256, 256>>>(W_out, wo0,  wo1,  V_ * H_);

    init_k<<<(B_ * H_) / 256, 256>>>(embedding, sos);

    GemmOps opIH = {ia0, ia1, wih0, wih1, b_ih, pgi};
    GemmOps opHH = {ha0, ha1, whh0, whh1, b_hh, pgh};
    GemmOps opO  = {ha0, ha1, wo0,  wo1,  b_out, plog};

    dim3 gOut(V_ / 128, B_ / 128);    // 16 x 64

    for (int t = 0; t < T_; t++) {
        uint32_t fk0, fk1;
        tf2x32(0u, 42u, 0u, (uint32_t)t, fk0, fk1);   // fold_in(key(42), t)

        // gates GEMM (gi+gh) with Gumbel(t) generation backfilled
        gates_gum<<<3584, 512, SMEM_TOT>>>(opIH, opHH, fk0, fk1);
        gru_ln<<<B_, 512>>>(ln_g, ln_b);
        // fused logits GEMM + sampling (finisher CTAs sample their m-block)
        logits_sample<<<gOut, 512, SMEM_TOT>>>(opO, etab, t, oSeq, oLp, oEnt);
    }
}

// round 14
// speedup vs baseline: 1.7352x; 1.7352x over previous
#include <cuda_runtime.h>
#include <cuda_fp16.h>
#include <cstdint>
#include <math.h>

#define B_  8192
#define H_  512
#define G3_ 1536
#define V_  2048
#define T_  24

// residual scale 2^11
#define RSC   2048.0f
#define RSCI  4.8828125e-4f

// ---------------------------------------------------------------------------
// Scratch (device globals: allocation-free)
// ---------------------------------------------------------------------------
__device__ float g_h[B_ * H_];
__device__ float g_gh[B_ * G3_];
__device__ float g_logits[B_ * V_];
__device__ float g_gum[(size_t)B_ * V_];     // per-step Gumbel noise
__device__ float g_GE[(size_t)V_ * G3_];     // embed_table @ Wih^T + b_ih
__device__ float g_gi0[128 * G3_];           // sos @ Wih^T + b_ih (row 0 used)
__device__ int   g_tok[B_];                  // sampled token per row

// scaled fp16x2 splits: X = X0 + X1 * 2^-11
__device__ __half g_IA0[128 * H_],  g_IA1[128 * H_];   // sos rows (prologue only)
__device__ __half g_E0[V_ * H_],    g_E1[V_ * H_];     // embed_table splits
__device__ __half g_HA0[B_ * H_],   g_HA1[B_ * H_];
__device__ __half g_Wih0[G3_ * H_], g_Wih1[G3_ * H_];
__device__ __half g_Whh0[G3_ * H_], g_Whh1[G3_ * H_];
__device__ __half g_Wo0[V_ * H_],   g_Wo1[V_ * H_];

// ---------------------------------------------------------------------------
// Threefry-2x32 (exact JAX replica)
// ---------------------------------------------------------------------------
__host__ __device__ __forceinline__ uint32_t rotl32(uint32_t v, int r) {
    return (v << r) | (v >> (32 - r));
}

__host__ __device__ __forceinline__ void tf2x32(uint32_t k0, uint32_t k1,
                                                uint32_t c0, uint32_t c1,
                                                uint32_t &o0, uint32_t &o1) {
    const uint32_t k2 = k0 ^ k1 ^ 0x1BD11BDAu;
    uint32_t a = c0, b = c1;
    a += k0; b += k1;
#define TFR(r) { a += b; b = rotl32(b, r); b ^= a; }
    TFR(13) TFR(15) TFR(26) TFR(6)
    a += k1; b += k2 + 1u;
    TFR(17) TFR(29) TFR(16) TFR(24)
    a += k2; b += k0 + 2u;
    TFR(13) TFR(15) TFR(26) TFR(6)
    a += k0; b += k1 + 3u;
    TFR(17) TFR(29) TFR(16) TFR(24)
    a += k1; b += k2 + 4u;
    TFR(13) TFR(15) TFR(26) TFR(6)
    a += k2; b += k0 + 5u;
#undef TFR
    o0 = a; o1 = b;
}

__device__ __forceinline__ float gumbelf(uint32_t bits) {
    float f = __uint_as_float((bits >> 9) | 0x3F800000u) - 1.0f;
    float u = fmaxf(1.17549435082228751e-38f, f);
    return -logf(-logf(u));
}

__device__ __forceinline__ float sigx(float v) {
    return 0.5f * tanhf(0.5f * v) + 0.5f;
}

// scaled fp16x2 split: x ≈ h0 + h1 * 2^-11
__device__ __forceinline__ void split2(float x, __half &h0, __half &h1) {
    h0 = __float2half_rn(x);
    float r = x - __half2float(h0);
    h1 = __float2half_rn(r * RSC);
}

// ---------------------------------------------------------------------------
// mma.sync / ldmatrix / cp.async primitives
// ---------------------------------------------------------------------------
__device__ __forceinline__ uint32_t smem_u32(const void* p) {
    uint32_t a;
    asm("{ .reg .u64 t; cvta.to.shared.u64 t, %1; cvt.u32.u64 %0, t; }"
        : "=r"(a) : "l"(p));
    return a;
}

__device__ __forceinline__ void ldsm4(uint32_t &r0, uint32_t &r1,
                                      uint32_t &r2, uint32_t &r3, uint32_t addr) {
    asm volatile("ldmatrix.sync.aligned.m8n8.x4.shared.b16 {%0,%1,%2,%3}, [%4];"
                 : "=r"(r0), "=r"(r1), "=r"(r2), "=r"(r3) : "r"(addr));
}

__device__ __forceinline__ void mma16816(float *d, const uint32_t *a,
                                         uint32_t b0, uint32_t b1) {
    asm volatile(
        "mma.sync.aligned.m16n8k16.row.col.f32.f16.f16.f32 "
        "{%0,%1,%2,%3},{%4,%5,%6,%7},{%8,%9},{%0,%1,%2,%3};"
        : "+f"(d[0]), "+f"(d[1]), "+f"(d[2]), "+f"(d[3])
        : "r"(a[0]), "r"(a[1]), "r"(a[2]), "r"(a[3]), "r"(b0), "r"(b1));
}

__device__ __forceinline__ void cp16(uint32_t saddr, const void *g) {
    asm volatile("cp.async.cg.shared.global [%0], [%1], 16;"
                 :: "r"(saddr), "l"(g));
}
#define CP_COMMIT() asm volatile("cp.async.commit_group;" ::: "memory")
#define CP_WAIT(n)  asm volatile("cp.async.wait_group %0;" :: "n"(n) : "memory")

struct GemmOps { const __half *a0, *a1, *b0, *b1;
                 const float *bias; float *c; };

#define TILE_B   8192
#define STAGE_B  (4 * TILE_B)
#define SMEM_TOT (2 * STAGE_B)

// ---------------------------------------------------------------------------
// Shared GEMM tile body (128x128 CTA tile, 512 thr, 16 warps 4x4).
// Proven at rel_err 1.8e-7 (R9/R11). Unchanged.
// ---------------------------------------------------------------------------
__device__ __forceinline__ void gemm_tile_body(const GemmOps &op, int m0, int n0,
                                               int N, char *smem) {
    const uint32_t sb = smem_u32(smem);
    const int tid = threadIdx.x;
    const int wid = tid >> 5;
    const int lane = tid & 31;
    const int wm = wid >> 2;
    const int wn = wid & 3;

    const __half *mats[4] = {
        op.a0 + (size_t)m0 * 512, op.a1 + (size_t)m0 * 512,
        op.b0 + (size_t)n0 * 512, op.b1 + (size_t)n0 * 512};

    auto issue = [&](int ch, int buf) {
        const uint32_t bbase = sb + (uint32_t)buf * STAGE_B;
#pragma unroll
        for (int s = 0; s < 4; ++s) {
            int seg = tid + s * 512;
            int m = seg >> 9;
            int w = seg & 511;
            int row = w >> 2;
            int u = w & 3;
            uint32_t bo = (uint32_t)(row << 6) + (uint32_t)(u << 4);
            uint32_t sw = bo ^ ((bo >> 3) & 0x30u);
            cp16(bbase + m * TILE_B + sw,
                 mats[m] + (size_t)row * 512 + (ch << 5) + (u << 3));
        }
        CP_COMMIT();
    };

    float hi[2][4][4], lo[2][4][4];
#pragma unroll
    for (int i = 0; i < 2; i++)
#pragma unroll
        for (int j = 0; j < 4; j++)
#pragma unroll
            for (int k = 0; k < 4; k++) { hi[i][j][k] = 0.0f; lo[i][j][k] = 0.0f; }

    issue(0, 0);

#pragma unroll 1
    for (int ch = 0; ch < 16; ++ch) {
        const int buf = ch & 1;
        if (ch < 15) { issue(ch + 1, buf ^ 1); CP_WAIT(1); }
        else         { CP_WAIT(0); }
        __syncthreads();

        const uint32_t stage = sb + (uint32_t)buf * STAGE_B;

#pragma unroll
        for (int ks = 0; ks < 2; ++ks) {
            const uint32_t kb = (uint32_t)(ks * 32) + (uint32_t)((lane >> 4) << 4);

            uint32_t bq[2][2][4];
#pragma unroll
            for (int sp = 0; sp < 2; ++sp) {
                const uint32_t Bt = stage + (2 + sp) * TILE_B;
#pragma unroll
                for (int nh = 0; nh < 2; ++nh) {
                    uint32_t row = (uint32_t)(wn * 32 + nh * 16 + (lane & 15));
                    uint32_t bo = (row << 6) + kb;
                    uint32_t sw = bo ^ ((bo >> 3) & 0x30u);
                    ldsm4(bq[sp][nh][0], bq[sp][nh][1], bq[sp][nh][2], bq[sp][nh][3],
                          Bt + sw);
                }
            }
            uint32_t af[2][2][4];
#pragma unroll
            for (int sp = 0; sp < 2; ++sp) {
                const uint32_t At = stage + sp * TILE_B;
#pragma unroll
                for (int mi = 0; mi < 2; ++mi) {
                    uint32_t row = (uint32_t)(wm * 32 + mi * 16 + (lane & 15));
                    uint32_t bo = (row << 6) + kb;
                    uint32_t sw = bo ^ ((bo >> 3) & 0x30u);
                    ldsm4(af[sp][mi][0], af[sp][mi][1], af[sp][mi][2], af[sp][mi][3],
                          At + sw);
                }
            }
#pragma unroll
            for (int mi = 0; mi < 2; ++mi)
#pragma unroll
                for (int ni = 0; ni < 4; ++ni) {
                    uint32_t b00 = bq[0][ni >> 1][ni & 1];
                    uint32_t b01 = bq[0][ni >> 1][(ni & 1) + 2];
                    uint32_t b10 = bq[1][ni >> 1][ni & 1];
                    uint32_t b11 = bq[1][ni >> 1][(ni & 1) + 2];
                    mma16816(hi[mi][ni], af[0][mi], b00, b01);
                    mma16816(lo[mi][ni], af[0][mi], b10, b11);
                    mma16816(lo[mi][ni], af[1][mi], b00, b01);
                }
        }
        __syncthreads();
    }

    const int tr = lane >> 2;
    const int tc = (lane & 3) << 1;
#pragma unroll
    for (int ni = 0; ni < 4; ++ni) {
        const int col = n0 + wn * 32 + ni * 8 + tc;
        const float bx = op.bias[col];
        const float by = op.bias[col + 1];
#pragma unroll
        for (int mi = 0; mi < 2; ++mi) {
            const int r0 = m0 + wm * 32 + mi * 16 + tr;
            float2 v0, v1;
            v0.x = fmaf(lo[mi][ni][0], RSCI, hi[mi][ni][0]) + bx;
            v0.y = fmaf(lo[mi][ni][1], RSCI, hi[mi][ni][1]) + by;
            v1.x = fmaf(lo[mi][ni][2], RSCI, hi[mi][ni][2]) + bx;
            v1.y = fmaf(lo[mi][ni][3], RSCI, hi[mi][ni][3]) + by;
            *(float2 *)(op.c + (size_t)r0 * N + col) = v0;
            *(float2 *)(op.c + (size_t)(r0 + 8) * N + col) = v1;
        }
    }
}

// Single-op GEMM: grid (n-tiles, m-tiles)
__global__ void __launch_bounds__(512)
gemm_f16x2(GemmOps op, int N) {
    extern __shared__ char smem[];
    gemm_tile_body(op, blockIdx.y << 7, blockIdx.x << 7, N, smem);
}

// ---------------------------------------------------------------------------
// gh GEMM + Gumbel generation, one launch:
//   blocks [0,768)      : gh tiles  (HA @ Whh^T)
//   blocks [768,2816)   : Gumbel(t) noise -> g_gum
// ---------------------------------------------------------------------------
__global__ void __launch_bounds__(512)
gh_gum(GemmOps opHH, uint32_t k0, uint32_t k1) {
    extern __shared__ char smem[];
    const int bid = blockIdx.x;
    if (bid < 768) {
        gemm_tile_body(opHH, (bid / 12) << 7, (bid % 12) << 7, G3_, smem);
        return;
    }
    const uint32_t gb = (uint32_t)(bid - 768);
    const uint32_t base = gb * 8192u + (uint32_t)threadIdx.x;
#pragma unroll
    for (int k = 0; k < 16; ++k) {
        uint32_t j = base + (uint32_t)(k << 9);
        uint32_t o0, o1;
        tf2x32(k0, k1, 0u, j, o0, o1);
        g_gum[j] = gumbelf(o0 ^ o1);
    }
}

// ---------------------------------------------------------------------------
// Sampling (R11-proven reductions); writes ONLY token index + outputs.
// ---------------------------------------------------------------------------
__global__ void __launch_bounds__(256) sample_k(
    int t, float *__restrict__ oSeq, float *__restrict__ oLp,
    float *__restrict__ oEnt) {
    const int b = blockIdx.x;
    const int tid = threadIdx.x;
    const int wid = tid >> 5;
    const int lane = tid & 31;

    __shared__ float sm[35];
    int *smi = (int *)sm;

    float xx[8], gg[8], e8[8];
    const float *L = g_logits + (size_t)b * V_;
    const float *G = g_gum + (size_t)b * V_;
#pragma unroll
    for (int i = 0; i < 8; i++) {
        int v = tid + i * 256;
        xx[i] = L[v];
        gg[i] = G[v];
    }

    // block max
    float m = -INFINITY;
#pragma unroll
    for (int i = 0; i < 8; i++) m = fmaxf(m, xx[i]);
#pragma unroll
    for (int o = 16; o > 0; o >>= 1) m = fmaxf(m, __shfl_xor_sync(~0u, m, o));
    if (lane == 0) sm[wid] = m;
    __syncthreads();
    if (tid < 32) {
        float v = (lane < 8) ? sm[lane] : -INFINITY;
#pragma unroll
        for (int o = 4; o > 0; o >>= 1) v = fmaxf(v, __shfl_xor_sync(~0u, v, o));
        if (lane == 0) sm[32] = v;
    }
    __syncthreads();
    m = sm[32];

    // block sum of exp(x - m)
    float ss = 0.0f;
#pragma unroll
    for (int i = 0; i < 8; i++) { e8[i] = expf(xx[i] - m); ss += e8[i]; }
#pragma unroll
    for (int o = 16; o > 0; o >>= 1) ss += __shfl_xor_sync(~0u, ss, o);
    if (lane == 0) sm[wid] = ss;
    __syncthreads();
    if (tid < 32) {
        float v = (lane < 8) ? sm[lane] : 0.0f;
#pragma unroll
        for (int o = 4; o > 0; o >>= 1) v += __shfl_xor_sync(~0u, v, o);
        if (lane == 0) sm[33] = v;
    }
    __syncthreads();
    float Lg = logf(sm[33]);
    float inv = expf(-Lg);
    __syncthreads();

    // per-element: lsm, entropy, gumbel argmax (first-index tie-break)
    float bv = -INFINITY, blsm = 0.0f, ent = 0.0f;
    int bi = 0x7FFFFFFF;
#pragma unroll
    for (int i = 0; i < 8; i++) {
        int v = tid + i * 256;
        float lsm = (xx[i] - m) - Lg;
        ent += (e8[i] * inv) * lsm;
        float val = lsm + gg[i];
        if (val > bv) { bv = val; bi = v; blsm = lsm; }
    }
#pragma unroll
    for (int o = 16; o > 0; o >>= 1) {
        float v2 = __shfl_xor_sync(~0u, bv, o);
        int   i2 = __shfl_xor_sync(~0u, bi, o);
        float l2 = __shfl_xor_sync(~0u, blsm, o);
        ent += __shfl_xor_sync(~0u, ent, o);
        if (v2 > bv || (v2 == bv && i2 < bi)) { bv = v2; bi = i2; blsm = l2; }
    }
    if (lane == 0) {
        sm[wid] = bv; sm[8 + wid] = ent; sm[16 + wid] = blsm; smi[24 + wid] = bi;
    }
    __syncthreads();
    if (tid < 32) {
        float v = (lane < 8) ? sm[lane] : -INFINITY;
        float e = (lane < 8) ? sm[8 + lane] : 0.0f;
        float l = (lane < 8) ? sm[16 + lane] : 0.0f;
        int   ix = (lane < 8) ? smi[24 + lane] : 0x7FFFFFFF;
#pragma unroll
        for (int o = 4; o > 0; o >>= 1) {
            float v2 = __shfl_xor_sync(~0u, v, o);
            int   i2 = __shfl_xor_sync(~0u, ix, o);
            float l2 = __shfl_xor_sync(~0u, l, o);
            e += __shfl_xor_sync(~0u, e, o);
            if (v2 > v || (v2 == v && i2 < ix)) { v = v2; ix = i2; l = l2; }
        }
        if (lane == 0) {
            oSeq[(size_t)b * T_ + t] = (float)ix;
            oLp [(size_t)b * T_ + t] = l;
            oEnt[(size_t)b * T_ + t] = -e;
            g_tok[b] = ix;
        }
    }
}

// ---------------------------------------------------------------------------
// GRU cell + LayerNorm; gi read via token indirection into GE (or gi0 at t=0).
// ---------------------------------------------------------------------------
__global__ void __launch_bounds__(512) gru_ln(const float *__restrict__ ln_g,
                                              const float *__restrict__ ln_b,
                                              int useTok) {
    const int b = blockIdx.x;
    const int j = threadIdx.x;
    const int wid = j >> 5;
    const int lane = j & 31;
    __shared__ float ws[16];
    __shared__ float bc[2];

    const float *gib = useTok ? (g_GE + (size_t)g_tok[b] * G3_) : g_gi0;
    const float *ghb = g_gh + (size_t)b * G3_;
    float hv = g_h[(size_t)b * H_ + j];

    float r = sigx(gib[j] + ghb[j]);
    float z = sigx(gib[512 + j] + ghb[512 + j]);
    float n = tanhf(gib[1024 + j] + r * ghb[1024 + j]);
    float hn = (1.0f - z) * n + z * hv;

    float s = hn;
#pragma unroll
    for (int o = 16; o > 0; o >>= 1) s += __shfl_xor_sync(0xFFFFFFFFu, s, o);
    if (lane == 0) ws[wid] = s;
    __syncthreads();
    if (j < 32) {
        float v = (j < 16) ? ws[j] : 0.0f;
#pragma unroll
        for (int o = 8; o > 0; o >>= 1) v += __shfl_xor_sync(0xFFFFFFFFu, v, o);
        if (j == 0) bc[0] = v * (1.0f / 512.0f);
    }
    __syncthreads();
    float mu = bc[0];

    float d = hn - mu;
    s = d * d;
#pragma unroll
    for (int o = 16; o > 0; o >>= 1) s += __shfl_xor_sync(0xFFFFFFFFu, s, o);
    if (lane == 0) ws[wid] = s;
    __syncthreads();
    if (j < 32) {
        float v = (j < 16) ? ws[j] : 0.0f;
#pragma unroll
        for (int o = 8; o > 0; o >>= 1) v += __shfl_xor_sync(0xFFFFFFFFu, v, o);
        if (j == 0) bc[1] = v * (1.0f / 512.0f);
    }
    __syncthreads();
    float var = bc[1];

    float out = d * rsqrtf(var + 1e-5f) * ln_g[j] + ln_b[j];
    size_t idx = (size_t)b * H_ + j;
    g_h[idx] = out;
    __half h0, h1;
    split2(out, h0, h1);
    g_HA0[idx] = h0; g_HA1[idx] = h1;
}

// ---------------------------------------------------------------------------
// Init: h/HA from embedding; sos splits into 128 IA rows
// ---------------------------------------------------------------------------
__global__ void __launch_bounds__(256) init_k(const float *__restrict__ emb,
                                              const float *__restrict__ sos) {
    int i = blockIdx.x * 256 + threadIdx.x;
    float x = emb[i];
    g_h[i] = x;
    __half h0, h1;
    split2(x, h0, h1);
    g_HA0[i] = h0; g_HA1[i] = h1;

    if (i < 128 * H_) {
        float y = sos[i & 511];
        split2(y, h0, h1);
        g_IA0[i] = h0; g_IA1[i] = h1;
    }
}

__global__ void __launch_bounds__(256) splitw_k(const float *__restrict__ src,
                                                __half *d0, __half *d1, int n) {
    int i = blockIdx.x * 256 + threadIdx.x;
    if (i < n) {
        __half a, b;
        split2(src[i], a, b);
        d0[i] = a; d1[i] = b;
    }
}

// ---------------------------------------------------------------------------
// Host launcher (graph-capturable; single stream, no allocations)
// ---------------------------------------------------------------------------
extern "C" void kernel_launch(void* const* d_in, const int* in_sizes, int n_in,
                              void* d_out, int out_size) {
    (void)in_sizes; (void)n_in; (void)out_size;
    const float* embedding = (const float*)d_in[0];
    const float* sos   = (const float*)d_in[2];
    const float* W_ih  = (const float*)d_in[3];
    const float* W_hh  = (const float*)d_in[4];
    const float* b_ih  = (const float*)d_in[5];
    const float* b_hh  = (const float*)d_in[6];
    const float* ln_g  = (const float*)d_in[7];
    const float* ln_b  = (const float*)d_in[8];
    const float* W_out = (const float*)d_in[9];
    const float* b_out = (const float*)d_in[10];
    const float* etab  = (const float*)d_in[11];

    float* out  = (float*)d_out;
    float* oSeq = out;
    float* oLp  = out + (size_t)B_ * T_;
    float* oEnt = out + (size_t)2 * B_ * T_;

    cudaFuncSetAttribute(gemm_f16x2, cudaFuncAttributeMaxDynamicSharedMemorySize,
                         SMEM_TOT);
    cudaFuncSetAttribute(gh_gum, cudaFuncAttributeMaxDynamicSharedMemorySize,
                         SMEM_TOT);

    float *pgh, *plog, *pGE, *pgi0;
    cudaGetSymbolAddress((void**)&pgh,  g_gh);
    cudaGetSymbolAddress((void**)&plog, g_logits);
    cudaGetSymbolAddress((void**)&pGE,  g_GE);
    cudaGetSymbolAddress((void**)&pgi0, g_gi0);

    __half *ia0, *ia1, *e0, *e1, *ha0, *ha1;
    __half *wih0, *wih1, *whh0, *whh1, *wo0, *wo1;
    cudaGetSymbolAddress((void**)&ia0, g_IA0); cudaGetSymbolAddress((void**)&ia1, g_IA1);
    cudaGetSymbolAddress((void**)&e0,  g_E0);  cudaGetSymbolAddress((void**)&e1,  g_E1);
    cudaGetSymbolAddress((void**)&ha0, g_HA0); cudaGetSymbolAddress((void**)&ha1, g_HA1);
    cudaGetSymbolAddress((void**)&wih0, g_Wih0); cudaGetSymbolAddress((void**)&wih1, g_Wih1);
    cudaGetSymbolAddress((void**)&whh0, g_Whh0); cudaGetSymbolAddress((void**)&whh1, g_Whh1);
    cudaGetSymbolAddress((void**)&wo0, g_Wo0); cudaGetSymbolAddress((void**)&wo1, g_Wo1);

    // ---- prologue ----
    splitw_k<<<(G3_ * H_ + 255) / 256, 256>>>(W_ih,  wih0, wih1, G3_ * H_);
    splitw_k<<<(G3_ * H_ + 255) / 256, 256>>>(W_hh,  whh0, whh1, G3_ * H_);
    splitw_k<<<(V_  * H_ + 255) / 256, 256>>>(W_out, wo0,  wo1,  V_ * H_);
    splitw_k<<<(V_  * H_ + 255) / 256, 256>>>(etab,  e0,   e1,   V_ * H_);
    init_k<<<(B_ * H_) / 256, 256>>>(embedding, sos);

    // GE = etab @ Wih^T + b_ih  (2048 x 1536); bit-identical rows to the
    // per-step gi GEMM this replaces.
    GemmOps opGE  = {e0, e1, wih0, wih1, b_ih, pGE};
    gemm_f16x2<<<dim3(G3_ / 128, V_ / 128), 512, SMEM_TOT>>>(opGE, G3_);
    // gi0 = sos @ Wih^T + b_ih  (row 0 of a 128-row tile)
    GemmOps opGI0 = {ia0, ia1, wih0, wih1, b_ih, pgi0};
    gemm_f16x2<<<dim3(G3_ / 128, 1), 512, SMEM_TOT>>>(opGI0, G3_);

    GemmOps opHH = {ha0, ha1, whh0, whh1, b_hh, pgh};
    GemmOps opO  = {ha0, ha1, wo0,  wo1,  b_out, plog};

    dim3 gOut(V_ / 128, B_ / 128);

    for (int t = 0; t < T_; t++) {
        uint32_t fk0, fk1;
        tf2x32(0u, 42u, 0u, (uint32_t)t, fk0, fk1);   // fold_in(key(42), t)

        // gh GEMM + Gumbel(t) generation in one launch
        gh_gum<<<2816, 512, SMEM_TOT>>>(opHH, fk0, fk1);
        // GRU + LN; gi via token indirection (gi0 broadcast at t=0)
        gru_ln<<<B_, 512>>>(ln_g, ln_b, t > 0 ? 1 : 0);
        // logits GEMM
        gemm_f16x2<<<gOut, 512, SMEM_TOT>>>(opO, V_);
        // sampling -> outputs + g_tok
        sample_k<<<B_, 256>>>(t, oSeq, oLp, oEnt);
    }
}

// round 15
// speedup vs baseline: 1.7657x; 1.0176x over previous
#include <cuda_runtime.h>
#include <cuda_fp16.h>
#include <cstdint>
#include <math.h>

#define B_  8192
#define H_  512
#define G3_ 1536
#define V_  2048
#define T_  24

// residual scale 2^11
#define RSC   2048.0f
#define RSCI  4.8828125e-4f

// ---------------------------------------------------------------------------
// Scratch (device globals: allocation-free)
// ---------------------------------------------------------------------------
__device__ float g_h[B_ * H_];
__device__ float g_gh[B_ * G3_];
__device__ float g_logits[B_ * V_];
__device__ float g_gumA[(size_t)B_ * V_];    // Gumbel noise, even steps
__device__ float g_gumB[(size_t)B_ * V_];    // Gumbel noise, odd steps
__device__ float g_GE[(size_t)V_ * G3_];     // embed_table @ Wih^T + b_ih
__device__ float g_gi0[128 * G3_];           // sos @ Wih^T + b_ih (row 0 used)
__device__ int   g_tok[B_];                  // sampled token per row

// scaled fp16x2 splits: X = X0 + X1 * 2^-11
__device__ __half g_IA0[128 * H_],  g_IA1[128 * H_];   // sos rows (prologue only)
__device__ __half g_E0[V_ * H_],    g_E1[V_ * H_];     // embed_table splits
__device__ __half g_HA0[B_ * H_],   g_HA1[B_ * H_];
__device__ __half g_Wih0[G3_ * H_], g_Wih1[G3_ * H_];
__device__ __half g_Whh0[G3_ * H_], g_Whh1[G3_ * H_];
__device__ __half g_Wo0[V_ * H_],   g_Wo1[V_ * H_];

// ---------------------------------------------------------------------------
// Threefry-2x32 (exact JAX replica)
// ---------------------------------------------------------------------------
__host__ __device__ __forceinline__ uint32_t rotl32(uint32_t v, int r) {
    return (v << r) | (v >> (32 - r));
}

__host__ __device__ __forceinline__ void tf2x32(uint32_t k0, uint32_t k1,
                                                uint32_t c0, uint32_t c1,
                                                uint32_t &o0, uint32_t &o1) {
    const uint32_t k2 = k0 ^ k1 ^ 0x1BD11BDAu;
    uint32_t a = c0, b = c1;
    a += k0; b += k1;
#define TFR(r) { a += b; b = rotl32(b, r); b ^= a; }
    TFR(13) TFR(15) TFR(26) TFR(6)
    a += k1; b += k2 + 1u;
    TFR(17) TFR(29) TFR(16) TFR(24)
    a += k2; b += k0 + 2u;
    TFR(13) TFR(15) TFR(26) TFR(6)
    a += k0; b += k1 + 3u;
    TFR(17) TFR(29) TFR(16) TFR(24)
    a += k1; b += k2 + 4u;
    TFR(13) TFR(15) TFR(26) TFR(6)
    a += k2; b += k0 + 5u;
#undef TFR
    o0 = a; o1 = b;
}

__device__ __forceinline__ float gumbelf(uint32_t bits) {
    float f = __uint_as_float((bits >> 9) | 0x3F800000u) - 1.0f;
    float u = fmaxf(1.17549435082228751e-38f, f);
    return -logf(-logf(u));
}

__device__ __forceinline__ float sigx(float v) {
    return 0.5f * tanhf(0.5f * v) + 0.5f;
}

// scaled fp16x2 split: x ≈ h0 + h1 * 2^-11
__device__ __forceinline__ void split2(float x, __half &h0, __half &h1) {
    h0 = __float2half_rn(x);
    float r = x - __half2float(h0);
    h1 = __float2half_rn(r * RSC);
}

// ---------------------------------------------------------------------------
// mma.sync / ldmatrix / cp.async primitives
// ---------------------------------------------------------------------------
__device__ __forceinline__ uint32_t smem_u32(const void* p) {
    uint32_t a;
    asm("{ .reg .u64 t; cvta.to.shared.u64 t, %1; cvt.u32.u64 %0, t; }"
        : "=r"(a) : "l"(p));
    return a;
}

__device__ __forceinline__ void ldsm4(uint32_t &r0, uint32_t &r1,
                                      uint32_t &r2, uint32_t &r3, uint32_t addr) {
    asm volatile("ldmatrix.sync.aligned.m8n8.x4.shared.b16 {%0,%1,%2,%3}, [%4];"
                 : "=r"(r0), "=r"(r1), "=r"(r2), "=r"(r3) : "r"(addr));
}

__device__ __forceinline__ void mma16816(float *d, const uint32_t *a,
                                         uint32_t b0, uint32_t b1) {
    asm volatile(
        "mma.sync.aligned.m16n8k16.row.col.f32.f16.f16.f32 "
        "{%0,%1,%2,%3},{%4,%5,%6,%7},{%8,%9},{%0,%1,%2,%3};"
        : "+f"(d[0]), "+f"(d[1]), "+f"(d[2]), "+f"(d[3])
        : "r"(a[0]), "r"(a[1]), "r"(a[2]), "r"(a[3]), "r"(b0), "r"(b1));
}

__device__ __forceinline__ void cp16(uint32_t saddr, const void *g) {
    asm volatile("cp.async.cg.shared.global [%0], [%1], 16;"
                 :: "r"(saddr), "l"(g));
}
#define CP_COMMIT() asm volatile("cp.async.commit_group;" ::: "memory")
#define CP_WAIT(n)  asm volatile("cp.async.wait_group %0;" :: "n"(n) : "memory")

struct GemmOps { const __half *a0, *a1, *b0, *b1;
                 const float *bias; float *c; };

#define TILE_B   8192
#define STAGE_B  (4 * TILE_B)
#define SMEM_TOT (2 * STAGE_B)

// ---------------------------------------------------------------------------
// Shared GEMM tile body (128x128 CTA tile, 512 thr, 16 warps 4x4).
// Proven at rel_err 1.8e-7 (R9/R11/R14). Unchanged.
// ---------------------------------------------------------------------------
__device__ __forceinline__ void gemm_tile_body(const GemmOps &op, int m0, int n0,
                                               int N, char *smem) {
    const uint32_t sb = smem_u32(smem);
    const int tid = threadIdx.x;
    const int wid = tid >> 5;
    const int lane = tid & 31;
    const int wm = wid >> 2;
    const int wn = wid & 3;

    const __half *mats[4] = {
        op.a0 + (size_t)m0 * 512, op.a1 + (size_t)m0 * 512,
        op.b0 + (size_t)n0 * 512, op.b1 + (size_t)n0 * 512};

    auto issue = [&](int ch, int buf) {
        const uint32_t bbase = sb + (uint32_t)buf * STAGE_B;
#pragma unroll
        for (int s = 0; s < 4; ++s) {
            int seg = tid + s * 512;
            int m = seg >> 9;
            int w = seg & 511;
            int row = w >> 2;
            int u = w & 3;
            uint32_t bo = (uint32_t)(row << 6) + (uint32_t)(u << 4);
            uint32_t sw = bo ^ ((bo >> 3) & 0x30u);
            cp16(bbase + m * TILE_B + sw,
                 mats[m] + (size_t)row * 512 + (ch << 5) + (u << 3));
        }
        CP_COMMIT();
    };

    float hi[2][4][4], lo[2][4][4];
#pragma unroll
    for (int i = 0; i < 2; i++)
#pragma unroll
        for (int j = 0; j < 4; j++)
#pragma unroll
            for (int k = 0; k < 4; k++) { hi[i][j][k] = 0.0f; lo[i][j][k] = 0.0f; }

    issue(0, 0);

#pragma unroll 1
    for (int ch = 0; ch < 16; ++ch) {
        const int buf = ch & 1;
        if (ch < 15) { issue(ch + 1, buf ^ 1); CP_WAIT(1); }
        else         { CP_WAIT(0); }
        __syncthreads();

        const uint32_t stage = sb + (uint32_t)buf * STAGE_B;

#pragma unroll
        for (int ks = 0; ks < 2; ++ks) {
            const uint32_t kb = (uint32_t)(ks * 32) + (uint32_t)((lane >> 4) << 4);

            uint32_t bq[2][2][4];
#pragma unroll
            for (int sp = 0; sp < 2; ++sp) {
                const uint32_t Bt = stage + (2 + sp) * TILE_B;
#pragma unroll
                for (int nh = 0; nh < 2; ++nh) {
                    uint32_t row = (uint32_t)(wn * 32 + nh * 16 + (lane & 15));
                    uint32_t bo = (row << 6) + kb;
                    uint32_t sw = bo ^ ((bo >> 3) & 0x30u);
                    ldsm4(bq[sp][nh][0], bq[sp][nh][1], bq[sp][nh][2], bq[sp][nh][3],
                          Bt + sw);
                }
            }
            uint32_t af[2][2][4];
#pragma unroll
            for (int sp = 0; sp < 2; ++sp) {
                const uint32_t At = stage + sp * TILE_B;
#pragma unroll
                for (int mi = 0; mi < 2; ++mi) {
                    uint32_t row = (uint32_t)(wm * 32 + mi * 16 + (lane & 15));
                    uint32_t bo = (row << 6) + kb;
                    uint32_t sw = bo ^ ((bo >> 3) & 0x30u);
                    ldsm4(af[sp][mi][0], af[sp][mi][1], af[sp][mi][2], af[sp][mi][3],
                          At + sw);
                }
            }
#pragma unroll
            for (int mi = 0; mi < 2; ++mi)
#pragma unroll
                for (int ni = 0; ni < 4; ++ni) {
                    uint32_t b00 = bq[0][ni >> 1][ni & 1];
                    uint32_t b01 = bq[0][ni >> 1][(ni & 1) + 2];
                    uint32_t b10 = bq[1][ni >> 1][ni & 1];
                    uint32_t b11 = bq[1][ni >> 1][(ni & 1) + 2];
                    mma16816(hi[mi][ni], af[0][mi], b00, b01);
                    mma16816(lo[mi][ni], af[0][mi], b10, b11);
                    mma16816(lo[mi][ni], af[1][mi], b00, b01);
                }
        }
        __syncthreads();
    }

    const int tr = lane >> 2;
    const int tc = (lane & 3) << 1;
#pragma unroll
    for (int ni = 0; ni < 4; ++ni) {
        const int col = n0 + wn * 32 + ni * 8 + tc;
        const float bx = op.bias[col];
        const float by = op.bias[col + 1];
#pragma unroll
        for (int mi = 0; mi < 2; ++mi) {
            const int r0 = m0 + wm * 32 + mi * 16 + tr;
            float2 v0, v1;
            v0.x = fmaf(lo[mi][ni][0], RSCI, hi[mi][ni][0]) + bx;
            v0.y = fmaf(lo[mi][ni][1], RSCI, hi[mi][ni][1]) + by;
            v1.x = fmaf(lo[mi][ni][2], RSCI, hi[mi][ni][2]) + bx;
            v1.y = fmaf(lo[mi][ni][3], RSCI, hi[mi][ni][3]) + by;
            *(float2 *)(op.c + (size_t)r0 * N + col) = v0;
            *(float2 *)(op.c + (size_t)(r0 + 8) * N + col) = v1;
        }
    }
}

// Single-op GEMM: grid (n-tiles, m-tiles) -- prologue only
__global__ void __launch_bounds__(512)
gemm_f16x2(GemmOps op, int N) {
    extern __shared__ char smem[];
    gemm_tile_body(op, blockIdx.y << 7, blockIdx.x << 7, N, smem);
}

// ---------------------------------------------------------------------------
// Gumbel block helper: 512 thr x 16 elems, gb in [0,2048)
// ---------------------------------------------------------------------------
__device__ __forceinline__ void gum_block(float *gum, uint32_t gb,
                                          uint32_t k0, uint32_t k1) {
    const uint32_t base = gb * 8192u + (uint32_t)threadIdx.x;
#pragma unroll
    for (int k = 0; k < 16; ++k) {
        uint32_t j = base + (uint32_t)(k << 9);
        uint32_t o0, o1;
        tf2x32(k0, k1, 0u, j, o0, o1);
        gum[j] = gumbelf(o0 ^ o1);
    }
}

// ---------------------------------------------------------------------------
// Prologue gh(0) + gum(0): blocks [0,768) gh tiles; [768,2816) gumbel
// ---------------------------------------------------------------------------
__global__ void __launch_bounds__(512)
gh_gum(GemmOps opHH, uint32_t k0, uint32_t k1, float *gum) {
    extern __shared__ char smem[];
    const int bid = blockIdx.x;
    if (bid < 768) {
        gemm_tile_body(opHH, (bid / 12) << 7, (bid % 12) << 7, G3_, smem);
        return;
    }
    gum_block(gum, (uint32_t)(bid - 768), k0, k1);
}

// ---------------------------------------------------------------------------
// Mega launch: everything that depends only on HA(t):
//   blocks [0,1024)     : logits(t) tiles   (HA @ Wo^T)   [on critical path]
//   blocks [1024,1792)  : gh(t+1) tiles     (HA @ Whh^T)
//   blocks [1792,3840)  : Gumbel(t+1) -> gumNext
// At the last step, launch only the first 1024 blocks.
// ---------------------------------------------------------------------------
__global__ void __launch_bounds__(512)
mega_k(GemmOps opO, GemmOps opHH, uint32_t k0, uint32_t k1, float *gumNext) {
    extern __shared__ char smem[];
    const int bid = blockIdx.x;
    if (bid < 1024) {
        gemm_tile_body(opO, (bid >> 4) << 7, (bid & 15) << 7, V_, smem);
        return;
    }
    if (bid < 1792) {
        const int local = bid - 1024;
        gemm_tile_body(opHH, (local / 12) << 7, (local % 12) << 7, G3_, smem);
        return;
    }
    gum_block(gumNext, (uint32_t)(bid - 1792), k0, k1);
}

// ---------------------------------------------------------------------------
// Sampling (R11/R14-proven reductions); writes outputs + g_tok.
// ---------------------------------------------------------------------------
__global__ void __launch_bounds__(256) sample_k(
    const float *__restrict__ gum, int t,
    float *__restrict__ oSeq, float *__restrict__ oLp, float *__restrict__ oEnt) {
    const int b = blockIdx.x;
    const int tid = threadIdx.x;
    const int wid = tid >> 5;
    const int lane = tid & 31;

    __shared__ float sm[35];
    int *smi = (int *)sm;

    float xx[8], gg[8], e8[8];
    const float *L = g_logits + (size_t)b * V_;
    const float *G = gum + (size_t)b * V_;
#pragma unroll
    for (int i = 0; i < 8; i++) {
        int v = tid + i * 256;
        xx[i] = L[v];
        gg[i] = G[v];
    }

    // block max
    float m = -INFINITY;
#pragma unroll
    for (int i = 0; i < 8; i++) m = fmaxf(m, xx[i]);
#pragma unroll
    for (int o = 16; o > 0; o >>= 1) m = fmaxf(m, __shfl_xor_sync(~0u, m, o));
    if (lane == 0) sm[wid] = m;
    __syncthreads();
    if (tid < 32) {
        float v = (lane < 8) ? sm[lane] : -INFINITY;
#pragma unroll
        for (int o = 4; o > 0; o >>= 1) v = fmaxf(v, __shfl_xor_sync(~0u, v, o));
        if (lane == 0) sm[32] = v;
    }
    __syncthreads();
    m = sm[32];

    // block sum of exp(x - m)
    float ss = 0.0f;
#pragma unroll
    for (int i = 0; i < 8; i++) { e8[i] = expf(xx[i] - m); ss += e8[i]; }
#pragma unroll
    for (int o = 16; o > 0; o >>= 1) ss += __shfl_xor_sync(~0u, ss, o);
    if (lane == 0) sm[wid] = ss;
    __syncthreads();
    if (tid < 32) {
        float v = (lane < 8) ? sm[lane] : 0.0f;
#pragma unroll
        for (int o = 4; o > 0; o >>= 1) v += __shfl_xor_sync(~0u, v, o);
        if (lane == 0) sm[33] = v;
    }
    __syncthreads();
    float Lg = logf(sm[33]);
    float inv = expf(-Lg);
    __syncthreads();

    // per-element: lsm, entropy, gumbel argmax (first-index tie-break)
    float bv = -INFINITY, blsm = 0.0f, ent = 0.0f;
    int bi = 0x7FFFFFFF;
#pragma unroll
    for (int i = 0; i < 8; i++) {
        int v = tid + i * 256;
        float lsm = (xx[i] - m) - Lg;
        ent += (e8[i] * inv) * lsm;
        float val = lsm + gg[i];
        if (val > bv) { bv = val; bi = v; blsm = lsm; }
    }
#pragma unroll
    for (int o = 16; o > 0; o >>= 1) {
        float v2 = __shfl_xor_sync(~0u, bv, o);
        int   i2 = __shfl_xor_sync(~0u, bi, o);
        float l2 = __shfl_xor_sync(~0u, blsm, o);
        ent += __shfl_xor_sync(~0u, ent, o);
        if (v2 > bv || (v2 == bv && i2 < bi)) { bv = v2; bi = i2; blsm = l2; }
    }
    if (lane == 0) {
        sm[wid] = bv; sm[8 + wid] = ent; sm[16 + wid] = blsm; smi[24 + wid] = bi;
    }
    __syncthreads();
    if (tid < 32) {
        float v = (lane < 8) ? sm[lane] : -INFINITY;
        float e = (lane < 8) ? sm[8 + lane] : 0.0f;
        float l = (lane < 8) ? sm[16 + lane] : 0.0f;
        int   ix = (lane < 8) ? smi[24 + lane] : 0x7FFFFFFF;
#pragma unroll
        for (int o = 4; o > 0; o >>= 1) {
            float v2 = __shfl_xor_sync(~0u, v, o);
            int   i2 = __shfl_xor_sync(~0u, ix, o);
            float l2 = __shfl_xor_sync(~0u, l, o);
            e += __shfl_xor_sync(~0u, e, o);
            if (v2 > v || (v2 == v && i2 < ix)) { v = v2; ix = i2; l = l2; }
        }
        if (lane == 0) {
            oSeq[(size_t)b * T_ + t] = (float)ix;
            oLp [(size_t)b * T_ + t] = l;
            oEnt[(size_t)b * T_ + t] = -e;
            g_tok[b] = ix;
        }
    }
}

// ---------------------------------------------------------------------------
// GRU cell + LayerNorm; gi read via token indirection into GE (or gi0 at t=0).
// ---------------------------------------------------------------------------
__global__ void __launch_bounds__(512) gru_ln(const float *__restrict__ ln_g,
                                              const float *__restrict__ ln_b,
                                              int useTok) {
    const int b = blockIdx.x;
    const int j = threadIdx.x;
    const int wid = j >> 5;
    const int lane = j & 31;
    __shared__ float ws[16];
    __shared__ float bc[2];

    const float *gib = useTok ? (g_GE + (size_t)g_tok[b] * G3_) : g_gi0;
    const float *ghb = g_gh + (size_t)b * G3_;
    float hv = g_h[(size_t)b * H_ + j];

    float r = sigx(gib[j] + ghb[j]);
    float z = sigx(gib[512 + j] + ghb[512 + j]);
    float n = tanhf(gib[1024 + j] + r * ghb[1024 + j]);
    float hn = (1.0f - z) * n + z * hv;

    float s = hn;
#pragma unroll
    for (int o = 16; o > 0; o >>= 1) s += __shfl_xor_sync(0xFFFFFFFFu, s, o);
    if (lane == 0) ws[wid] = s;
    __syncthreads();
    if (j < 32) {
        float v = (j < 16) ? ws[j] : 0.0f;
#pragma unroll
        for (int o = 8; o > 0; o >>= 1) v += __shfl_xor_sync(0xFFFFFFFFu, v, o);
        if (j == 0) bc[0] = v * (1.0f / 512.0f);
    }
    __syncthreads();
    float mu = bc[0];

    float d = hn - mu;
    s = d * d;
#pragma unroll
    for (int o = 16; o > 0; o >>= 1) s += __shfl_xor_sync(0xFFFFFFFFu, s, o);
    if (lane == 0) ws[wid] = s;
    __syncthreads();
    if (j < 32) {
        float v = (j < 16) ? ws[j] : 0.0f;
#pragma unroll
        for (int o = 8; o > 0; o >>= 1) v += __shfl_xor_sync(0xFFFFFFFFu, v, o);
        if (j == 0) bc[1] = v * (1.0f / 512.0f);
    }
    __syncthreads();
    float var = bc[1];

    float out = d * rsqrtf(var + 1e-5f) * ln_g[j] + ln_b[j];
    size_t idx = (size_t)b * H_ + j;
    g_h[idx] = out;
    __half h0, h1;
    split2(out, h0, h1);
    g_HA0[idx] = h0; g_HA1[idx] = h1;
}

// ---------------------------------------------------------------------------
// Init: h/HA from embedding; sos splits into 128 IA rows
// ---------------------------------------------------------------------------
__global__ void __launch_bounds__(256) init_k(const float *__restrict__ emb,
                                              const float *__restrict__ sos) {
    int i = blockIdx.x * 256 + threadIdx.x;
    float x = emb[i];
    g_h[i] = x;
    __half h0, h1;
    split2(x, h0, h1);
    g_HA0[i] = h0; g_HA1[i] = h1;

    if (i < 128 * H_) {
        float y = sos[i & 511];
        split2(y, h0, h1);
        g_IA0[i] = h0; g_IA1[i] = h1;
    }
}

__global__ void __launch_bounds__(256) splitw_k(const float *__restrict__ src,
                                                __half *d0, __half *d1, int n) {
    int i = blockIdx.x * 256 + threadIdx.x;
    if (i < n) {
        __half a, b;
        split2(src[i], a, b);
        d0[i] = a; d1[i] = b;
    }
}

// ---------------------------------------------------------------------------
// Host launcher (graph-capturable; single stream, no allocations)
// ---------------------------------------------------------------------------
extern "C" void kernel_launch(void* const* d_in, const int* in_sizes, int n_in,
                              void* d_out, int out_size) {
    (void)in_sizes; (void)n_in; (void)out_size;
    const float* embedding = (const float*)d_in[0];
    const float* sos   = (const float*)d_in[2];
    const float* W_ih  = (const float*)d_in[3];
    const float* W_hh  = (const float*)d_in[4];
    const float* b_ih  = (const float*)d_in[5];
    const float* b_hh  = (const float*)d_in[6];
    const float* ln_g  = (const float*)d_in[7];
    const float* ln_b  = (const float*)d_in[8];
    const float* W_out = (const float*)d_in[9];
    const float* b_out = (const float*)d_in[10];
    const float* etab  = (const float*)d_in[11];

    float* out  = (float*)d_out;
    float* oSeq = out;
    float* oLp  = out + (size_t)B_ * T_;
    float* oEnt = out + (size_t)2 * B_ * T_;

    cudaFuncSetAttribute(gemm_f16x2, cudaFuncAttributeMaxDynamicSharedMemorySize,
                         SMEM_TOT);
    cudaFuncSetAttribute(gh_gum, cudaFuncAttributeMaxDynamicSharedMemorySize,
                         SMEM_TOT);
    cudaFuncSetAttribute(mega_k, cudaFuncAttributeMaxDynamicSharedMemorySize,
                         SMEM_TOT);

    float *pgh, *plog, *pGE, *pgi0, *pgumA, *pgumB;
    cudaGetSymbolAddress((void**)&pgh,   g_gh);
    cudaGetSymbolAddress((void**)&plog,  g_logits);
    cudaGetSymbolAddress((void**)&pGE,   g_GE);
    cudaGetSymbolAddress((void**)&pgi0,  g_gi0);
    cudaGetSymbolAddress((void**)&pgumA, g_gumA);
    cudaGetSymbolAddress((void**)&pgumB, g_gumB);

    __half *ia0, *ia1, *e0, *e1, *ha0, *ha1;
    __half *wih0, *wih1, *whh0, *whh1, *wo0, *wo1;
    cudaGetSymbolAddress((void**)&ia0, g_IA0); cudaGetSymbolAddress((void**)&ia1, g_IA1);
    cudaGetSymbolAddress((void**)&e0,  g_E0);  cudaGetSymbolAddress((void**)&e1,  g_E1);
    cudaGetSymbolAddress((void**)&ha0, g_HA0); cudaGetSymbolAddress((void**)&ha1, g_HA1);
    cudaGetSymbolAddress((void**)&wih0, g_Wih0); cudaGetSymbolAddress((void**)&wih1, g_Wih1);
    cudaGetSymbolAddress((void**)&whh0, g_Whh0); cudaGetSymbolAddress((void**)&whh1, g_Whh1);
    cudaGetSymbolAddress((void**)&wo0, g_Wo0); cudaGetSymbolAddress((void**)&wo1, g_Wo1);

    // ---- prologue ----
    splitw_k<<<(G3_ * H_ + 255) / 256, 256>>>(W_ih,  wih0, wih1, G3_ * H_);
    splitw_k<<<(G3_ * H_ + 255) / 256, 256>>>(W_hh,  whh0, whh1, G3_ * H_);
    splitw_k<<<(V_  * H_ + 255) / 256, 256>>>(W_out, wo0,  wo1,  V_ * H_);
    splitw_k<<<(V_  * H_ + 255) / 256, 256>>>(etab,  e0,   e1,   V_ * H_);
    init_k<<<(B_ * H_) / 256, 256>>>(embedding, sos);

    // GE = etab @ Wih^T + b_ih (bit-identical rows to per-step gi GEMM)
    GemmOps opGE  = {e0, e1, wih0, wih1, b_ih, pGE};
    gemm_f16x2<<<dim3(G3_ / 128, V_ / 128), 512, SMEM_TOT>>>(opGE, G3_);
    // gi0 = sos @ Wih^T + b_ih
    GemmOps opGI0 = {ia0, ia1, wih0, wih1, b_ih, pgi0};
    gemm_f16x2<<<dim3(G3_ / 128, 1), 512, SMEM_TOT>>>(opGI0, G3_);

    GemmOps opHH = {ha0, ha1, whh0, whh1, b_hh, pgh};
    GemmOps opO  = {ha0, ha1, wo0,  wo1,  b_out, plog};

    // gh(0) + gum(0) (gum(0) -> buffer A)
    {
        uint32_t fk0, fk1;
        tf2x32(0u, 42u, 0u, 0u, fk0, fk1);
        gh_gum<<<2816, 512, SMEM_TOT>>>(opHH, fk0, fk1, pgumA);
    }

    for (int t = 0; t < T_; t++) {
        float *gumCur  = (t & 1) ? pgumB : pgumA;
        float *gumNext = (t & 1) ? pgumA : pgumB;

        // GRU + LN (gh(t) ready; gi via token indirection, gi0 at t=0)
        gru_ln<<<B_, 512>>>(ln_g, ln_b, t > 0 ? 1 : 0);

        // mega: logits(t) [+ gh(t+1) + gum(t+1) when another step follows]
        if (t < T_ - 1) {
            uint32_t nk0, nk1;
            tf2x32(0u, 42u, 0u, (uint32_t)(t + 1), nk0, nk1);
            mega_k<<<3840, 512, SMEM_TOT>>>(opO, opHH, nk0, nk1, gumNext);
        } else {
            mega_k<<<1024, 512, SMEM_TOT>>>(opO, opHH, 0u, 0u, gumNext);
        }

        // sampling -> outputs + g_tok (reads gum(t))
        sample_k<<<B_, 256>>>(gumCur, t, oSeq, oLp, oEnt);
    }
}

// round 16
// speedup vs baseline: 1.8047x; 1.0221x over previous
#include <cuda_runtime.h>
#include <cuda_fp16.h>
#include <cstdint>
#include <math.h>

#define B_  8192
#define H_  512
#define G3_ 1536
#define V_  2048
#define T_  24

// residual scale 2^11
#define RSC   2048.0f
#define RSCI  4.8828125e-4f

// ---------------------------------------------------------------------------
// Scratch (device globals: allocation-free)
// ---------------------------------------------------------------------------
__device__ float g_h[B_ * H_];
__device__ float g_gh[B_ * G3_];
__device__ float g_logits[B_ * V_];
__device__ float g_gumA[(size_t)B_ * V_];    // Gumbel noise, even steps
__device__ float g_gumB[(size_t)B_ * V_];    // Gumbel noise, odd steps
__device__ float g_GE[(size_t)V_ * G3_];     // embed_table @ Wih^T + b_ih
__device__ float g_gi0[128 * G3_];           // sos @ Wih^T + b_ih (row 0 used)
__device__ int   g_tok[B_];                  // sampled token per row

// scaled fp16x2 splits: X = X0 + X1 * 2^-11
__device__ __half g_IA0[128 * H_],  g_IA1[128 * H_];   // sos rows (prologue only)
__device__ __half g_E0[V_ * H_],    g_E1[V_ * H_];     // embed_table splits
__device__ __half g_HA0[B_ * H_],   g_HA1[B_ * H_];
__device__ __half g_Wih0[G3_ * H_], g_Wih1[G3_ * H_];
__device__ __half g_Whh0[G3_ * H_], g_Whh1[G3_ * H_];
__device__ __half g_Wo0[V_ * H_],   g_Wo1[V_ * H_];

// ---------------------------------------------------------------------------
// Threefry-2x32 (exact JAX replica)
// ---------------------------------------------------------------------------
__host__ __device__ __forceinline__ uint32_t rotl32(uint32_t v, int r) {
    return (v << r) | (v >> (32 - r));
}

__host__ __device__ __forceinline__ void tf2x32(uint32_t k0, uint32_t k1,
                                                uint32_t c0, uint32_t c1,
                                                uint32_t &o0, uint32_t &o1) {
    const uint32_t k2 = k0 ^ k1 ^ 0x1BD11BDAu;
    uint32_t a = c0, b = c1;
    a += k0; b += k1;
#define TFR(r) { a += b; b = rotl32(b, r); b ^= a; }
    TFR(13) TFR(15) TFR(26) TFR(6)
    a += k1; b += k2 + 1u;
    TFR(17) TFR(29) TFR(16) TFR(24)
    a += k2; b += k0 + 2u;
    TFR(13) TFR(15) TFR(26) TFR(6)
    a += k0; b += k1 + 3u;
    TFR(17) TFR(29) TFR(16) TFR(24)
    a += k1; b += k2 + 4u;
    TFR(13) TFR(15) TFR(26) TFR(6)
    a += k2; b += k0 + 5u;
#undef TFR
    o0 = a; o1 = b;
}

__device__ __forceinline__ float gumbelf(uint32_t bits) {
    float f = __uint_as_float((bits >> 9) | 0x3F800000u) - 1.0f;
    float u = fmaxf(1.17549435082228751e-38f, f);
    return -logf(-logf(u));
}

__device__ __forceinline__ float sigx(float v) {
    return 0.5f * tanhf(0.5f * v) + 0.5f;
}

// scaled fp16x2 split: x ≈ h0 + h1 * 2^-11
__device__ __forceinline__ void split2(float x, __half &h0, __half &h1) {
    h0 = __float2half_rn(x);
    float r = x - __half2float(h0);
    h1 = __float2half_rn(r * RSC);
}

// ---------------------------------------------------------------------------
// mma.sync / ldmatrix / cp.async primitives
// ---------------------------------------------------------------------------
__device__ __forceinline__ uint32_t smem_u32(const void* p) {
    uint32_t a;
    asm("{ .reg .u64 t; cvta.to.shared.u64 t, %1; cvt.u32.u64 %0, t; }"
        : "=r"(a) : "l"(p));
    return a;
}

__device__ __forceinline__ void ldsm4(uint32_t &r0, uint32_t &r1,
                                      uint32_t &r2, uint32_t &r3, uint32_t addr) {
    asm volatile("ldmatrix.sync.aligned.m8n8.x4.shared.b16 {%0,%1,%2,%3}, [%4];"
                 : "=r"(r0), "=r"(r1), "=r"(r2), "=r"(r3) : "r"(addr));
}

__device__ __forceinline__ void mma16816(float *d, const uint32_t *a,
                                         uint32_t b0, uint32_t b1) {
    asm volatile(
        "mma.sync.aligned.m16n8k16.row.col.f32.f16.f16.f32 "
        "{%0,%1,%2,%3},{%4,%5,%6,%7},{%8,%9},{%0,%1,%2,%3};"
        : "+f"(d[0]), "+f"(d[1]), "+f"(d[2]), "+f"(d[3])
        : "r"(a[0]), "r"(a[1]), "r"(a[2]), "r"(a[3]), "r"(b0), "r"(b1));
}

__device__ __forceinline__ void cp16(uint32_t saddr, const void *g) {
    asm volatile("cp.async.cg.shared.global [%0], [%1], 16;"
                 :: "r"(saddr), "l"(g));
}
#define CP_COMMIT() asm volatile("cp.async.commit_group;" ::: "memory")
#define CP_WAIT(n)  asm volatile("cp.async.wait_group %0;" :: "n"(n) : "memory")

struct GemmOps { const __half *a0, *a1, *b0, *b1;
                 const float *bias; float *c; };

#define TILE_B   8192
#define STAGE_B  (4 * TILE_B)
#define SMEM_TOT (2 * STAGE_B)

// ---------------------------------------------------------------------------
// Shared GEMM tile body (128x128 CTA tile, 512 thr, 16 warps 4x4).
// Proven at rel_err 1.8e-7 (R9/R11/R14/R15). Unchanged.
// ---------------------------------------------------------------------------
__device__ __forceinline__ void gemm_tile_body(const GemmOps &op, int m0, int n0,
                                               int N, char *smem) {
    const uint32_t sb = smem_u32(smem);
    const int tid = threadIdx.x;
    const int wid = tid >> 5;
    const int lane = tid & 31;
    const int wm = wid >> 2;
    const int wn = wid & 3;

    const __half *mats[4] = {
        op.a0 + (size_t)m0 * 512, op.a1 + (size_t)m0 * 512,
        op.b0 + (size_t)n0 * 512, op.b1 + (size_t)n0 * 512};

    auto issue = [&](int ch, int buf) {
        const uint32_t bbase = sb + (uint32_t)buf * STAGE_B;
#pragma unroll
        for (int s = 0; s < 4; ++s) {
            int seg = tid + s * 512;
            int m = seg >> 9;
            int w = seg & 511;
            int row = w >> 2;
            int u = w & 3;
            uint32_t bo = (uint32_t)(row << 6) + (uint32_t)(u << 4);
            uint32_t sw = bo ^ ((bo >> 3) & 0x30u);
            cp16(bbase + m * TILE_B + sw,
                 mats[m] + (size_t)row * 512 + (ch << 5) + (u << 3));
        }
        CP_COMMIT();
    };

    float hi[2][4][4], lo[2][4][4];
#pragma unroll
    for (int i = 0; i < 2; i++)
#pragma unroll
        for (int j = 0; j < 4; j++)
#pragma unroll
            for (int k = 0; k < 4; k++) { hi[i][j][k] = 0.0f; lo[i][j][k] = 0.0f; }

    issue(0, 0);

#pragma unroll 1
    for (int ch = 0; ch < 16; ++ch) {
        const int buf = ch & 1;
        if (ch < 15) { issue(ch + 1, buf ^ 1); CP_WAIT(1); }
        else         { CP_WAIT(0); }
        __syncthreads();

        const uint32_t stage = sb + (uint32_t)buf * STAGE_B;

#pragma unroll
        for (int ks = 0; ks < 2; ++ks) {
            const uint32_t kb = (uint32_t)(ks * 32) + (uint32_t)((lane >> 4) << 4);

            uint32_t bq[2][2][4];
#pragma unroll
            for (int sp = 0; sp < 2; ++sp) {
                const uint32_t Bt = stage + (2 + sp) * TILE_B;
#pragma unroll
                for (int nh = 0; nh < 2; ++nh) {
                    uint32_t row = (uint32_t)(wn * 32 + nh * 16 + (lane & 15));
                    uint32_t bo = (row << 6) + kb;
                    uint32_t sw = bo ^ ((bo >> 3) & 0x30u);
                    ldsm4(bq[sp][nh][0], bq[sp][nh][1], bq[sp][nh][2], bq[sp][nh][3],
                          Bt + sw);
                }
            }
            uint32_t af[2][2][4];
#pragma unroll
            for (int sp = 0; sp < 2; ++sp) {
                const uint32_t At = stage + sp * TILE_B;
#pragma unroll
                for (int mi = 0; mi < 2; ++mi) {
                    uint32_t row = (uint32_t)(wm * 32 + mi * 16 + (lane & 15));
                    uint32_t bo = (row << 6) + kb;
                    uint32_t sw = bo ^ ((bo >> 3) & 0x30u);
                    ldsm4(af[sp][mi][0], af[sp][mi][1], af[sp][mi][2], af[sp][mi][3],
                          At + sw);
                }
            }
#pragma unroll
            for (int mi = 0; mi < 2; ++mi)
#pragma unroll
                for (int ni = 0; ni < 4; ++ni) {
                    uint32_t b00 = bq[0][ni >> 1][ni & 1];
                    uint32_t b01 = bq[0][ni >> 1][(ni & 1) + 2];
                    uint32_t b10 = bq[1][ni >> 1][ni & 1];
                    uint32_t b11 = bq[1][ni >> 1][(ni & 1) + 2];
                    mma16816(hi[mi][ni], af[0][mi], b00, b01);
                    mma16816(lo[mi][ni], af[0][mi], b10, b11);
                    mma16816(lo[mi][ni], af[1][mi], b00, b01);
                }
        }
        __syncthreads();
    }

    const int tr = lane >> 2;
    const int tc = (lane & 3) << 1;
#pragma unroll
    for (int ni = 0; ni < 4; ++ni) {
        const int col = n0 + wn * 32 + ni * 8 + tc;
        const float bx = op.bias[col];
        const float by = op.bias[col + 1];
#pragma unroll
        for (int mi = 0; mi < 2; ++mi) {
            const int r0 = m0 + wm * 32 + mi * 16 + tr;
            float2 v0, v1;
            v0.x = fmaf(lo[mi][ni][0], RSCI, hi[mi][ni][0]) + bx;
            v0.y = fmaf(lo[mi][ni][1], RSCI, hi[mi][ni][1]) + by;
            v1.x = fmaf(lo[mi][ni][2], RSCI, hi[mi][ni][2]) + bx;
            v1.y = fmaf(lo[mi][ni][3], RSCI, hi[mi][ni][3]) + by;
            *(float2 *)(op.c + (size_t)r0 * N + col) = v0;
            *(float2 *)(op.c + (size_t)(r0 + 8) * N + col) = v1;
        }
    }
}

// Single-op GEMM: grid (n-tiles, m-tiles) -- prologue only
__global__ void __launch_bounds__(512)
gemm_f16x2(GemmOps op, int N) {
    extern __shared__ char smem[];
    gemm_tile_body(op, blockIdx.y << 7, blockIdx.x << 7, N, smem);
}

// ---------------------------------------------------------------------------
// Gumbel block helper: 512 thr x 16 elems, gb in [0,2048)
// ---------------------------------------------------------------------------
__device__ __forceinline__ void gum_block(float *gum, uint32_t gb,
                                          uint32_t k0, uint32_t k1) {
    const uint32_t base = gb * 8192u + (uint32_t)threadIdx.x;
#pragma unroll
    for (int k = 0; k < 16; ++k) {
        uint32_t j = base + (uint32_t)(k << 9);
        uint32_t o0, o1;
        tf2x32(k0, k1, 0u, j, o0, o1);
        gum[j] = gumbelf(o0 ^ o1);
    }
}

// ---------------------------------------------------------------------------
// Prologue gh(0) + gum(0): blocks [0,768) gh tiles; [768,2816) gumbel
// ---------------------------------------------------------------------------
__global__ void __launch_bounds__(512)
gh_gum(GemmOps opHH, uint32_t k0, uint32_t k1, float *gum) {
    extern __shared__ char smem[];
    const int bid = blockIdx.x;
    if (bid < 768) {
        gemm_tile_body(opHH, (bid / 12) << 7, (bid % 12) << 7, G3_, smem);
        return;
    }
    gum_block(gum, (uint32_t)(bid - 768), k0, k1);
}

// ---------------------------------------------------------------------------
// Mega launch: everything that depends only on HA(t):
//   blocks [0,1024)     : logits(t) tiles   (HA @ Wo^T)   [on critical path]
//   blocks [1024,1792)  : gh(t+1) tiles     (HA @ Whh^T)
//   blocks [1792,3840)  : Gumbel(t+1) -> gumNext
// At the last step, launch only the first 1024 blocks.
// ---------------------------------------------------------------------------
__global__ void __launch_bounds__(512)
mega_k(GemmOps opO, GemmOps opHH, uint32_t k0, uint32_t k1, float *gumNext) {
    extern __shared__ char smem[];
    const int bid = blockIdx.x;
    if (bid < 1024) {
        gemm_tile_body(opO, (bid >> 4) << 7, (bid & 15) << 7, V_, smem);
        return;
    }
    if (bid < 1792) {
        const int local = bid - 1024;
        gemm_tile_body(opHH, (local / 12) << 7, (local % 12) << 7, G3_, smem);
        return;
    }
    gum_block(gumNext, (uint32_t)(bid - 1792), k0, k1);
}

// ---------------------------------------------------------------------------
// Fused sampling + GRU/LN for the NEXT step (row-local):
//   phase 1: sample(t) for row b (proven R14 code; writes outputs + tok)
//   phase 2 (doGru): GRU+LN(t+1) for row b using GE[tok] and gh(t+1)
//            (gh(t+1) was produced by mega(t), which precedes in-stream).
// Reduction trees replicate the 512-thread gru_ln bit-exactly: warp w
// reduces units 32w+lane and 256+32w+lane with identical lane order,
// storing partials at ws[w] / ws[w+8]; final 16-partial combine unchanged.
// ---------------------------------------------------------------------------
__global__ void __launch_bounds__(256) sample_gru(
    const float *__restrict__ gum, int t, int doGru,
    const float *__restrict__ ln_g, const float *__restrict__ ln_b,
    float *__restrict__ oSeq, float *__restrict__ oLp, float *__restrict__ oEnt) {
    const int b = blockIdx.x;
    const int tid = threadIdx.x;
    const int wid = tid >> 5;
    const int lane = tid & 31;

    __shared__ float sm[35];
    __shared__ float ws[16];
    __shared__ float bc[2];
    int *smi = (int *)sm;

    // ---------------- phase 1: sampling (verbatim R14) ----------------
    float xx[8], gg[8], e8[8];
    {
        const float *L = g_logits + (size_t)b * V_;
        const float *G = gum + (size_t)b * V_;
#pragma unroll
        for (int i = 0; i < 8; i++) {
            int v = tid + i * 256;
            xx[i] = L[v];
            gg[i] = G[v];
        }
    }

    float m = -INFINITY;
#pragma unroll
    for (int i = 0; i < 8; i++) m = fmaxf(m, xx[i]);
#pragma unroll
    for (int o = 16; o > 0; o >>= 1) m = fmaxf(m, __shfl_xor_sync(~0u, m, o));
    if (lane == 0) sm[wid] = m;
    __syncthreads();
    if (tid < 32) {
        float v = (lane < 8) ? sm[lane] : -INFINITY;
#pragma unroll
        for (int o = 4; o > 0; o >>= 1) v = fmaxf(v, __shfl_xor_sync(~0u, v, o));
        if (lane == 0) sm[32] = v;
    }
    __syncthreads();
    m = sm[32];

    float ss = 0.0f;
#pragma unroll
    for (int i = 0; i < 8; i++) { e8[i] = expf(xx[i] - m); ss += e8[i]; }
#pragma unroll
    for (int o = 16; o > 0; o >>= 1) ss += __shfl_xor_sync(~0u, ss, o);
    if (lane == 0) sm[wid] = ss;
    __syncthreads();
    if (tid < 32) {
        float v = (lane < 8) ? sm[lane] : 0.0f;
#pragma unroll
        for (int o = 4; o > 0; o >>= 1) v += __shfl_xor_sync(~0u, v, o);
        if (lane == 0) sm[33] = v;
    }
    __syncthreads();
    float Lg = logf(sm[33]);
    float inv = expf(-Lg);
    __syncthreads();

    float bv = -INFINITY, blsm = 0.0f, ent = 0.0f;
    int bi = 0x7FFFFFFF;
#pragma unroll
    for (int i = 0; i < 8; i++) {
        int v = tid + i * 256;
        float lsm = (xx[i] - m) - Lg;
        ent += (e8[i] * inv) * lsm;
        float val = lsm + gg[i];
        if (val > bv) { bv = val; bi = v; blsm = lsm; }
    }
#pragma unroll
    for (int o = 16; o > 0; o >>= 1) {
        float v2 = __shfl_xor_sync(~0u, bv, o);
        int   i2 = __shfl_xor_sync(~0u, bi, o);
        float l2 = __shfl_xor_sync(~0u, blsm, o);
        ent += __shfl_xor_sync(~0u, ent, o);
        if (v2 > bv || (v2 == bv && i2 < bi)) { bv = v2; bi = i2; blsm = l2; }
    }
    if (lane == 0) {
        sm[wid] = bv; sm[8 + wid] = ent; sm[16 + wid] = blsm; smi[24 + wid] = bi;
    }
    __syncthreads();
    if (tid < 32) {
        float v = (lane < 8) ? sm[lane] : -INFINITY;
        float e = (lane < 8) ? sm[8 + lane] : 0.0f;
        float l = (lane < 8) ? sm[16 + lane] : 0.0f;
        int   ix = (lane < 8) ? smi[24 + lane] : 0x7FFFFFFF;
#pragma unroll
        for (int o = 4; o > 0; o >>= 1) {
            float v2 = __shfl_xor_sync(~0u, v, o);
            int   i2 = __shfl_xor_sync(~0u, ix, o);
            float l2 = __shfl_xor_sync(~0u, l, o);
            e += __shfl_xor_sync(~0u, e, o);
            if (v2 > v || (v2 == v && i2 < ix)) { v = v2; ix = i2; l = l2; }
        }
        if (lane == 0) {
            oSeq[(size_t)b * T_ + t] = (float)ix;
            oLp [(size_t)b * T_ + t] = l;
            oEnt[(size_t)b * T_ + t] = -e;
            smi[34] = ix;
        }
    }
    __syncthreads();
    const int tok = smi[34];

    if (!doGru) return;

    // ---------------- phase 2: GRU + LN for step t+1, row b ----------------
    const float *gib = g_GE + (size_t)tok * G3_;
    const float *ghb = g_gh + (size_t)b * G3_;
    const int j1 = tid, j2 = tid + 256;

    float hv1 = g_h[(size_t)b * H_ + j1];
    float hv2 = g_h[(size_t)b * H_ + j2];

    float r1 = sigx(gib[j1] + ghb[j1]);
    float z1 = sigx(gib[512 + j1] + ghb[512 + j1]);
    float n1 = tanhf(gib[1024 + j1] + r1 * ghb[1024 + j1]);
    float hn1 = (1.0f - z1) * n1 + z1 * hv1;

    float r2 = sigx(gib[j2] + ghb[j2]);
    float z2 = sigx(gib[512 + j2] + ghb[512 + j2]);
    float n2 = tanhf(gib[1024 + j2] + r2 * ghb[1024 + j2]);
    float hn2 = (1.0f - z2) * n2 + z2 * hv2;

    // mean (bit-identical tree to 512-thread gru_ln)
    float s1 = hn1, s2 = hn2;
#pragma unroll
    for (int o = 16; o > 0; o >>= 1) {
        s1 += __shfl_xor_sync(0xFFFFFFFFu, s1, o);
        s2 += __shfl_xor_sync(0xFFFFFFFFu, s2, o);
    }
    if (lane == 0) { ws[wid] = s1; ws[wid + 8] = s2; }
    __syncthreads();
    if (tid < 32) {
        float v = (lane < 16) ? ws[lane] : 0.0f;
#pragma unroll
        for (int o = 8; o > 0; o >>= 1) v += __shfl_xor_sync(0xFFFFFFFFu, v, o);
        if (lane == 0) bc[0] = v * (1.0f / 512.0f);
    }
    __syncthreads();
    float mu = bc[0];

    // variance
    float d1 = hn1 - mu, d2 = hn2 - mu;
    s1 = d1 * d1; s2 = d2 * d2;
#pragma unroll
    for (int o = 16; o > 0; o >>= 1) {
        s1 += __shfl_xor_sync(0xFFFFFFFFu, s1, o);
        s2 += __shfl_xor_sync(0xFFFFFFFFu, s2, o);
    }
    if (lane == 0) { ws[wid] = s1; ws[wid + 8] = s2; }
    __syncthreads();
    if (tid < 32) {
        float v = (lane < 16) ? ws[lane] : 0.0f;
#pragma unroll
        for (int o = 8; o > 0; o >>= 1) v += __shfl_xor_sync(0xFFFFFFFFu, v, o);
        if (lane == 0) bc[1] = v * (1.0f / 512.0f);
    }
    __syncthreads();
    float rs = rsqrtf(bc[1] + 1e-5f);

    float out1 = d1 * rs * ln_g[j1] + ln_b[j1];
    float out2 = d2 * rs * ln_g[j2] + ln_b[j2];

    size_t i1 = (size_t)b * H_ + j1;
    size_t i2 = (size_t)b * H_ + j2;
    g_h[i1] = out1; g_h[i2] = out2;
    __half h0, h1;
    split2(out1, h0, h1); g_HA0[i1] = h0; g_HA1[i1] = h1;
    split2(out2, h0, h1); g_HA0[i2] = h0; g_HA1[i2] = h1;
}

// ---------------------------------------------------------------------------
// GRU cell + LayerNorm (prologue t=0 only; gi from gi0 broadcast)
// ---------------------------------------------------------------------------
__global__ void __launch_bounds__(512) gru_ln(const float *__restrict__ ln_g,
                                              const float *__restrict__ ln_b) {
    const int b = blockIdx.x;
    const int j = threadIdx.x;
    const int wid = j >> 5;
    const int lane = j & 31;
    __shared__ float ws[16];
    __shared__ float bc[2];

    const float *gib = g_gi0;
    const float *ghb = g_gh + (size_t)b * G3_;
    float hv = g_h[(size_t)b * H_ + j];

    float r = sigx(gib[j] + ghb[j]);
    float z = sigx(gib[512 + j] + ghb[512 + j]);
    float n = tanhf(gib[1024 + j] + r * ghb[1024 + j]);
    float hn = (1.0f - z) * n + z * hv;

    float s = hn;
#pragma unroll
    for (int o = 16; o > 0; o >>= 1) s += __shfl_xor_sync(0xFFFFFFFFu, s, o);
    if (lane == 0) ws[wid] = s;
    __syncthreads();
    if (j < 32) {
        float v = (j < 16) ? ws[j] : 0.0f;
#pragma unroll
        for (int o = 8; o > 0; o >>= 1) v += __shfl_xor_sync(0xFFFFFFFFu, v, o);
        if (j == 0) bc[0] = v * (1.0f / 512.0f);
    }
    __syncthreads();
    float mu = bc[0];

    float d = hn - mu;
    s = d * d;
#pragma unroll
    for (int o = 16; o > 0; o >>= 1) s += __shfl_xor_sync(0xFFFFFFFFu, s, o);
    if (lane == 0) ws[wid] = s;
    __syncthreads();
    if (j < 32) {
        float v = (j < 16) ? ws[j] : 0.0f;
#pragma unroll
        for (int o = 8; o > 0; o >>= 1) v += __shfl_xor_sync(0xFFFFFFFFu, v, o);
        if (j == 0) bc[1] = v * (1.0f / 512.0f);
    }
    __syncthreads();
    float var = bc[1];

    float out = d * rsqrtf(var + 1e-5f) * ln_g[j] + ln_b[j];
    size_t idx = (size_t)b * H_ + j;
    g_h[idx] = out;
    __half h0, h1;
    split2(out, h0, h1);
    g_HA0[idx] = h0; g_HA1[idx] = h1;
}

// ---------------------------------------------------------------------------
// Init + weight splits
// ---------------------------------------------------------------------------
__global__ void __launch_bounds__(256) init_k(const float *__restrict__ emb,
                                              const float *__restrict__ sos) {
    int i = blockIdx.x * 256 + threadIdx.x;
    float x = emb[i];
    g_h[i] = x;
    __half h0, h1;
    split2(x, h0, h1);
    g_HA0[i] = h0; g_HA1[i] = h1;

    if (i < 128 * H_) {
        float y = sos[i & 511];
        split2(y, h0, h1);
        g_IA0[i] = h0; g_IA1[i] = h1;
    }
}

__global__ void __launch_bounds__(256) splitw_k(const float *__restrict__ src,
                                                __half *d0, __half *d1, int n) {
    int i = blockIdx.x * 256 + threadIdx.x;
    if (i < n) {
        __half a, b;
        split2(src[i], a, b);
        d0[i] = a; d1[i] = b;
    }
}

// ---------------------------------------------------------------------------
// Host launcher (graph-capturable; single stream, no allocations)
// ---------------------------------------------------------------------------
extern "C" void kernel_launch(void* const* d_in, const int* in_sizes, int n_in,
                              void* d_out, int out_size) {
    (void)in_sizes; (void)n_in; (void)out_size;
    const float* embedding = (const float*)d_in[0];
    const float* sos   = (const float*)d_in[2];
    const float* W_ih  = (const float*)d_in[3];
    const float* W_hh  = (const float*)d_in[4];
    const float* b_ih  = (const float*)d_in[5];
    const float* b_hh  = (const float*)d_in[6];
    const float* ln_g  = (const float*)d_in[7];
    const float* ln_b  = (const float*)d_in[8];
    const float* W_out = (const float*)d_in[9];
    const float* b_out = (const float*)d_in[10];
    const float* etab  = (const float*)d_in[11];

    float* out  = (float*)d_out;
    float* oSeq = out;
    float* oLp  = out + (size_t)B_ * T_;
    float* oEnt = out + (size_t)2 * B_ * T_;

    cudaFuncSetAttribute(gemm_f16x2, cudaFuncAttributeMaxDynamicSharedMemorySize,
                         SMEM_TOT);
    cudaFuncSetAttribute(gh_gum, cudaFuncAttributeMaxDynamicSharedMemorySize,
                         SMEM_TOT);
    cudaFuncSetAttribute(mega_k, cudaFuncAttributeMaxDynamicSharedMemorySize,
                         SMEM_TOT);

    float *pgh, *plog, *pGE, *pgi0, *pgumA, *pgumB;
    cudaGetSymbolAddress((void**)&pgh,   g_gh);
    cudaGetSymbolAddress((void**)&plog,  g_logits);
    cudaGetSymbolAddress((void**)&pGE,   g_GE);
    cudaGetSymbolAddress((void**)&pgi0,  g_gi0);
    cudaGetSymbolAddress((void**)&pgumA, g_gumA);
    cudaGetSymbolAddress((void**)&pgumB, g_gumB);

    __half *ia0, *ia1, *e0, *e1, *ha0, *ha1;
    __half *wih0, *wih1, *whh0, *whh1, *wo0, *wo1;
    cudaGetSymbolAddress((void**)&ia0, g_IA0); cudaGetSymbolAddress((void**)&ia1, g_IA1);
    cudaGetSymbolAddress((void**)&e0,  g_E0);  cudaGetSymbolAddress((void**)&e1,  g_E1);
    cudaGetSymbolAddress((void**)&ha0, g_HA0); cudaGetSymbolAddress((void**)&ha1, g_HA1);
    cudaGetSymbolAddress((void**)&wih0, g_Wih0); cudaGetSymbolAddress((void**)&wih1, g_Wih1);
    cudaGetSymbolAddress((void**)&whh0, g_Whh0); cudaGetSymbolAddress((void**)&whh1, g_Whh1);
    cudaGetSymbolAddress((void**)&wo0, g_Wo0); cudaGetSymbolAddress((void**)&wo1, g_Wo1);

    // ---- prologue ----
    splitw_k<<<(G3_ * H_ + 255) / 256, 256>>>(W_ih,  wih0, wih1, G3_ * H_);
    splitw_k<<<(G3_ * H_ + 255) / 256, 256>>>(W_hh,  whh0, whh1, G3_ * H_);
    splitw_k<<<(V_  * H_ + 255) / 256, 256>>>(W_out, wo0,  wo1,  V_ * H_);
    splitw_k<<<(V_  * H_ + 255) / 256, 256>>>(etab,  e0,   e1,   V_ * H_);
    init_k<<<(B_ * H_) / 256, 256>>>(embedding, sos);

    // GE = etab @ Wih^T + b_ih (bit-identical rows to per-step gi GEMM)
    GemmOps opGE  = {e0, e1, wih0, wih1, b_ih, pGE};
    gemm_f16x2<<<dim3(G3_ / 128, V_ / 128), 512, SMEM_TOT>>>(opGE, G3_);
    // gi0 = sos @ Wih^T + b_ih
    GemmOps opGI0 = {ia0, ia1, wih0, wih1, b_ih, pgi0};
    gemm_f16x2<<<dim3(G3_ / 128, 1), 512, SMEM_TOT>>>(opGI0, G3_);

    GemmOps opHH = {ha0, ha1, whh0, whh1, b_hh, pgh};
    GemmOps opO  = {ha0, ha1, wo0,  wo1,  b_out, plog};

    // gh(0) + gum(0) (gum(0) -> buffer A), then h(0) via prologue gru_ln
    {
        uint32_t fk0, fk1;
        tf2x32(0u, 42u, 0u, 0u, fk0, fk1);
        gh_gum<<<2816, 512, SMEM_TOT>>>(opHH, fk0, fk1, pgumA);
    }
    gru_ln<<<B_, 512>>>(ln_g, ln_b);

    for (int t = 0; t < T_; t++) {
        float *gumCur  = (t & 1) ? pgumB : pgumA;
        float *gumNext = (t & 1) ? pgumA : pgumB;

        // mega: logits(t) [+ gh(t+1) + gum(t+1) when another step follows]
        if (t < T_ - 1) {
            uint32_t nk0, nk1;
            tf2x32(0u, 42u, 0u, (uint32_t)(t + 1), nk0, nk1);
            mega_k<<<3840, 512, SMEM_TOT>>>(opO, opHH, nk0, nk1, gumNext);
        } else {
            mega_k<<<1024, 512, SMEM_TOT>>>(opO, opHH, 0u, 0u, gumNext);
        }

        // fused: sample(t) + GRU/LN(t+1) (GRU skipped at last step)
        sample_gru<<<B_, 256>>>(gumCur, t, t < T_ - 1 ? 1 : 0,
                                ln_g, ln_b, oSeq, oLp, oEnt);
    }
}